// round 2
// baseline (speedup 1.0000x reference)
#include <cuda_runtime.h>
#include <cuda_bf16.h>
#include <cstdint>

// Problem constants
#define BB 16
#define CC 256
#define C8 32
#define HH 96
#define WW 96
#define HW (HH*WW)          // 9216
#define KK 11

// ---------------- scratch (static device allocations; allowed) ----------------
#define SZ_SMALL (BB*C8*HW)      // 4,718,592
#define SZ_BIG   ((size_t)BB*CC*HW) // 37,748,736
#define SZ_E     ((size_t)BB*HH*WW*96) // 14,155,776
#define WT_SIZE  1802240

__device__ float g_wT[WT_SIZE];
__device__ float g_qh[SZ_SMALL];
__device__ float g_qw[SZ_SMALL];
__device__ float g_kh[SZ_SMALL];
__device__ float g_kw[SZ_SMALL];
__device__ float g_vh[SZ_BIG];
__device__ float g_vw[SZ_BIG];
__device__ float g_eh[SZ_E];
__device__ float g_ew[SZ_E];
__device__ float g_oh[SZ_BIG];
__device__ float g_ow[SZ_BIG];

// wT offsets (floats)
#define OFF_VH 0
#define OFF_VW 720896
#define OFF_QH 1441792
#define OFF_QW 1531904
#define OFF_KH 1622016
#define OFF_KW 1712128

// ---------------- weight transpose: w[o][c][t] -> wT[t][c][o] ----------------
__global__ void transposeW_kernel(const float* __restrict__ w, float* __restrict__ wT, int O)
{
    int i = blockIdx.x * 256 + threadIdx.x;
    int total = O * CC * KK;
    if (i < total) {
        int o = i / (CC * KK);
        int rem = i % (CC * KK);
        int c = rem / KK;
        int t = rem % KK;
        wT[((size_t)t * CC + c) * O + o] = w[i];
    }
}

// ---------------- separable conv as sum of shifted GEMMs ----------------
// y[b,o,p] = bias[o] + sum_t sum_c wT[t][c][o] * x[b,c,p + sh*stride], masked
template<int TO, int TP>
__global__ __launch_bounds__((TO/8)*(TP/8))
void conv_sep_kernel(const float* __restrict__ x,
                     const float* __restrict__ wT,
                     const float* __restrict__ bias,
                     float* __restrict__ y,
                     int O, int isVert)
{
    constexpr int CK = 8;
    constexpr int NTHR = (TO/8)*(TP/8);
    __shared__ float Ws[CK][TO];
    __shared__ float Xs[CK][TP];

    const int tid = threadIdx.x;
    const int pbase = blockIdx.x * TP;
    const int obase = blockIdx.y * TO;
    const int b = blockIdx.z;
    const float* xb = x + (size_t)b * CC * HW;

    float acc[8][8];
#pragma unroll
    for (int i = 0; i < 8; i++)
#pragma unroll
        for (int j = 0; j < 8; j++) acc[i][j] = 0.f;

    const int ox = tid % (TO/8);
    const int px = tid / (TO/8);

    for (int t = 0; t < KK; ++t) {
        const int sh = t - 5;
        const int off = isVert ? sh * WW : sh;
        for (int c0 = 0; c0 < CC; c0 += CK) {
            // stage weights: coalesced over o
#pragma unroll
            for (int l = tid; l < CK*TO; l += NTHR) {
                int cc = l / TO, oo = l % TO;
                Ws[cc][oo] = wT[((size_t)t * CC + (c0 + cc)) * O + obase + oo];
            }
            // stage shifted x: coalesced over p, masked at the shifted border
#pragma unroll
            for (int l = tid; l < CK*TP; l += NTHR) {
                int cc = l / TP, pp = l % TP;
                int p = pbase + pp;
                int coord = isVert ? (p / WW) : (p % WW);
                float v = 0.f;
                if ((unsigned)(coord + sh) < (unsigned)WW)
                    v = xb[(size_t)(c0 + cc) * HW + p + off];
                Xs[cc][pp] = v;
            }
            __syncthreads();
#pragma unroll
            for (int cc = 0; cc < CK; ++cc) {
                float a[8], bv[8];
#pragma unroll
                for (int i = 0; i < 8; i++) a[i] = Ws[cc][ox*8 + i];
#pragma unroll
                for (int j = 0; j < 8; j++) bv[j] = Xs[cc][px*8 + j];
#pragma unroll
                for (int i = 0; i < 8; i++)
#pragma unroll
                    for (int j = 0; j < 8; j++)
                        acc[i][j] += a[i] * bv[j];
            }
            __syncthreads();
        }
    }
#pragma unroll
    for (int i = 0; i < 8; i++) {
        int o = obase + ox*8 + i;
        float bs = bias[o];
        float* yp = y + ((size_t)b * O + o) * HW + pbase + px*8;
#pragma unroll
        for (int j = 0; j < 8; j++) yp[j] = acc[i][j] + bs;
    }
}

// ---------------- e_h: per (b,w), E[h][H] = sum_c Q[c][h] K[c][H] ----------------
__global__ __launch_bounds__(256)
void eh_kernel(const float* __restrict__ qh, const float* __restrict__ kh,
               float* __restrict__ eh)
{
    const int w = blockIdx.x;
    const int b = blockIdx.y;
    __shared__ float Qs[C8][HH];
    __shared__ float Ks[C8][HH];
    const int tid = threadIdx.x;
    const float* qb = qh + (size_t)b * C8 * HW + w;
    const float* kb = kh + (size_t)b * C8 * HW + w;
    for (int l = tid; l < C8 * HH; l += 256) {
        int c = l / HH, h = l % HH;
        Qs[c][h] = qb[(size_t)c * HW + h * WW];
        Ks[c][h] = kb[(size_t)c * HW + h * WW];
    }
    __syncthreads();
    const int h0 = (tid / 16) * 6;
    const int H0 = (tid % 16) * 6;
    float acc[6][6];
#pragma unroll
    for (int i = 0; i < 6; i++)
#pragma unroll
        for (int j = 0; j < 6; j++) acc[i][j] = 0.f;
    for (int c = 0; c < C8; ++c) {
        float q[6], k[6];
#pragma unroll
        for (int i = 0; i < 6; i++) q[i] = Qs[c][h0 + i];
#pragma unroll
        for (int j = 0; j < 6; j++) k[j] = Ks[c][H0 + j];
#pragma unroll
        for (int i = 0; i < 6; i++)
#pragma unroll
            for (int j = 0; j < 6; j++) acc[i][j] += q[i] * k[j];
    }
    float* ep = eh + ((size_t)b * WW + w) * HH * 96;
#pragma unroll
    for (int i = 0; i < 6; i++)
#pragma unroll
        for (int j = 0; j < 6; j++)
            ep[(h0 + i) * 96 + H0 + j] = acc[i][j];
}

// ---------------- e_w: per (b,h), E[w][W] = sum_c Q[c][w] K[c][W] ----------------
__global__ __launch_bounds__(256)
void ew_kernel(const float* __restrict__ qw, const float* __restrict__ kw,
               float* __restrict__ ew)
{
    const int h = blockIdx.x;
    const int b = blockIdx.y;
    __shared__ float Qs[C8][WW];
    __shared__ float Ks[C8][WW];
    const int tid = threadIdx.x;
    const float* qb = qw + (size_t)b * C8 * HW + (size_t)h * WW;
    const float* kb = kw + (size_t)b * C8 * HW + (size_t)h * WW;
    for (int l = tid; l < C8 * WW; l += 256) {
        int c = l / WW, w = l % WW;
        Qs[c][w] = qb[(size_t)c * HW + w];
        Ks[c][w] = kb[(size_t)c * HW + w];
    }
    __syncthreads();
    const int w0 = (tid / 16) * 6;
    const int W0 = (tid % 16) * 6;
    float acc[6][6];
#pragma unroll
    for (int i = 0; i < 6; i++)
#pragma unroll
        for (int j = 0; j < 6; j++) acc[i][j] = 0.f;
    for (int c = 0; c < C8; ++c) {
        float q[6], k[6];
#pragma unroll
        for (int i = 0; i < 6; i++) q[i] = Qs[c][w0 + i];
#pragma unroll
        for (int j = 0; j < 6; j++) k[j] = Ks[c][W0 + j];
#pragma unroll
        for (int i = 0; i < 6; i++)
#pragma unroll
            for (int j = 0; j < 6; j++) acc[i][j] += q[i] * k[j];
    }
    float* ep = ew + ((size_t)b * HH + h) * WW * 96;
#pragma unroll
    for (int i = 0; i < 6; i++)
#pragma unroll
        for (int j = 0; j < 6; j++)
            ep[(w0 + i) * 96 + W0 + j] = acc[i][j];
}

// ---------------- softmax over concat(e_h row, e_w row), in-place ----------------
__global__ __launch_bounds__(256)
void softmax_kernel(float* __restrict__ eh, float* __restrict__ ew)
{
    const int warp = threadIdx.x / 32;
    const int lane = threadIdx.x % 32;
    const int r = blockIdx.x * 8 + warp;   // r < 147456
    const int b = r / HW;
    const int rem = r % HW;
    const int h = rem / WW;
    const int w = rem % WW;
    float* ehp = eh + (((size_t)b * WW + w) * HH + h) * 96;
    float* ewp = ew + (((size_t)b * HH + h) * WW + w) * 96;

    float vh[3], vw[3];
    float m = -3.0e38f;
#pragma unroll
    for (int j = 0; j < 3; j++) {
        int H = lane + 32 * j;
        float a = (H == h) ? -3.0e38f : ehp[H];
        float c = ewp[H];
        vh[j] = a; vw[j] = c;
        m = fmaxf(m, fmaxf(a, c));
    }
#pragma unroll
    for (int s = 16; s > 0; s >>= 1)
        m = fmaxf(m, __shfl_xor_sync(0xffffffffu, m, s));
    float sum = 0.f;
#pragma unroll
    for (int j = 0; j < 3; j++) {
        vh[j] = __expf(vh[j] - m);
        vw[j] = __expf(vw[j] - m);
        sum += vh[j] + vw[j];
    }
#pragma unroll
    for (int s = 16; s > 0; s >>= 1)
        sum += __shfl_xor_sync(0xffffffffu, sum, s);
    float inv = 1.0f / sum;
#pragma unroll
    for (int j = 0; j < 3; j++) {
        int H = lane + 32 * j;
        ehp[H] = vh[j] * inv;
        ewp[H] = vw[j] * inv;
    }
}

// ---------------- out_h: per (b,w,cblk): out[c,h] = sum_H V[c,H] A[h,H] ----------------
__global__ __launch_bounds__(256)
void outh_kernel(const float* __restrict__ vh, const float* __restrict__ ah,
                 float* __restrict__ oh)
{
    extern __shared__ float sm[];
    float* As = sm;               // [96][96]
    float* Vs = sm + 96 * 96;     // [96][32]  Vs[H*32+c]
    const int w = blockIdx.x;
    const int c0 = blockIdx.y * 32;
    const int b = blockIdx.z;
    const int tid = threadIdx.x;

    const float* ab = ah + ((size_t)b * WW + w) * 9216;
    for (int l = tid; l < 9216; l += 256) As[l] = ab[l];
    for (int l = tid; l < 96 * 32; l += 256) {
        int Hc = l / 32, c = l % 32;
        Vs[Hc * 32 + c] = vh[((size_t)b * CC + c0 + c) * HW + Hc * WW + w];
    }
    __syncthreads();

    const int c = tid % 32;
    const int hg = tid / 32;  // 8 groups of 12 h
    float acc[12];
#pragma unroll
    for (int k = 0; k < 12; k++) acc[k] = 0.f;
    for (int Hc = 0; Hc < 96; ++Hc) {
        float v = Vs[Hc * 32 + c];
#pragma unroll
        for (int k = 0; k < 12; k++)
            acc[k] += v * As[(hg * 12 + k) * 96 + Hc];
    }
#pragma unroll
    for (int k = 0; k < 12; k++) {
        int h = hg * 12 + k;
        oh[((size_t)b * CC + c0 + c) * HW + h * WW + w] = acc[k];
    }
}

// ---------------- out_w: per (b,h,cblk): out[c,w] = sum_W V[c,W] A[w,W] ----------------
__global__ __launch_bounds__(256)
void outw_kernel(const float* __restrict__ vw, const float* __restrict__ aw,
                 float* __restrict__ ow)
{
    extern __shared__ float sm[];
    float* As = sm;               // [96][96]
    float* Vs = sm + 96 * 96;     // [96][33] padded: Vs[W*33+c]
    const int h = blockIdx.x;
    const int c0 = blockIdx.y * 32;
    const int b = blockIdx.z;
    const int tid = threadIdx.x;

    const float* ab = aw + ((size_t)b * HH + h) * 9216;
    for (int l = tid; l < 9216; l += 256) As[l] = ab[l];
    for (int l = tid; l < 96 * 32; l += 256) {
        int c = l / 96, Wc = l % 96;
        Vs[Wc * 33 + c] = vw[((size_t)b * CC + c0 + c) * HW + (size_t)h * WW + Wc];
    }
    __syncthreads();

    const int c = tid % 32;
    const int wg = tid / 32;
    float acc[12];
#pragma unroll
    for (int k = 0; k < 12; k++) acc[k] = 0.f;
    for (int Wc = 0; Wc < 96; ++Wc) {
        float v = Vs[Wc * 33 + c];
#pragma unroll
        for (int k = 0; k < 12; k++)
            acc[k] += v * As[(wg * 12 + k) * 96 + Wc];
    }
#pragma unroll
    for (int k = 0; k < 12; k++) {
        int w = wg * 12 + k;
        ow[((size_t)b * CC + c0 + c) * HW + (size_t)h * WW + w] = acc[k];
    }
}

// ---------------- final combine: out = gamma*(oh+ow) + x ----------------
__global__ __launch_bounds__(256)
void combine_kernel(const float* __restrict__ x, const float* __restrict__ oh,
                    const float* __restrict__ ow, const float* __restrict__ gamma,
                    float* __restrict__ out)
{
    size_t i = (size_t)blockIdx.x * 256 + threadIdx.x;  // float4 index, total 9437184
    const float4* x4 = (const float4*)x;
    const float4* a4 = (const float4*)oh;
    const float4* b4 = (const float4*)ow;
    float4* o4 = (float4*)out;
    float g = gamma[0];
    float4 xa = x4[i], aa = a4[i], bb = b4[i];
    float4 r;
    r.x = g * (aa.x + bb.x) + xa.x;
    r.y = g * (aa.y + bb.y) + xa.y;
    r.z = g * (aa.z + bb.z) + xa.z;
    r.w = g * (aa.w + bb.w) + xa.w;
    o4[i] = r;
}

// ---------------- launch ----------------
extern "C" void kernel_launch(void* const* d_in, const int* in_sizes, int n_in,
                              void* d_out, int out_size)
{
    const float* x    = (const float*)d_in[0];
    const float* wq_h = (const float*)d_in[1];
    const float* bq_h = (const float*)d_in[2];
    const float* wq_w = (const float*)d_in[3];
    const float* bq_w = (const float*)d_in[4];
    const float* wk_h = (const float*)d_in[5];
    const float* bk_h = (const float*)d_in[6];
    const float* wk_w = (const float*)d_in[7];
    const float* bk_w = (const float*)d_in[8];
    const float* wv_h = (const float*)d_in[9];
    const float* bv_h = (const float*)d_in[10];
    const float* wv_w = (const float*)d_in[11];
    const float* bv_w = (const float*)d_in[12];
    const float* gamma= (const float*)d_in[13];
    float* out = (float*)d_out;

    float *wT, *qh, *qw, *kh, *kw, *vh, *vw, *eh, *ew, *oh, *ow;
    cudaGetSymbolAddress((void**)&wT, g_wT);
    cudaGetSymbolAddress((void**)&qh, g_qh);
    cudaGetSymbolAddress((void**)&qw, g_qw);
    cudaGetSymbolAddress((void**)&kh, g_kh);
    cudaGetSymbolAddress((void**)&kw, g_kw);
    cudaGetSymbolAddress((void**)&vh, g_vh);
    cudaGetSymbolAddress((void**)&vw, g_vw);
    cudaGetSymbolAddress((void**)&eh, g_eh);
    cudaGetSymbolAddress((void**)&ew, g_ew);
    cudaGetSymbolAddress((void**)&oh, g_oh);
    cudaGetSymbolAddress((void**)&ow, g_ow);

    // 1) transpose weights to [t][c][o]
    transposeW_kernel<<<(CC*CC*KK + 255)/256, 256>>>(wv_h, wT + OFF_VH, CC);
    transposeW_kernel<<<(CC*CC*KK + 255)/256, 256>>>(wv_w, wT + OFF_VW, CC);
    transposeW_kernel<<<(C8*CC*KK + 255)/256, 256>>>(wq_h, wT + OFF_QH, C8);
    transposeW_kernel<<<(C8*CC*KK + 255)/256, 256>>>(wq_w, wT + OFF_QW, C8);
    transposeW_kernel<<<(C8*CC*KK + 255)/256, 256>>>(wk_h, wT + OFF_KH, C8);
    transposeW_kernel<<<(C8*CC*KK + 255)/256, 256>>>(wk_w, wT + OFF_KW, C8);

    // 2) convolutions
    dim3 gb(HW/128, CC/128, BB);
    conv_sep_kernel<128,128><<<gb, 256>>>(x, wT + OFF_VH, bv_h, vh, CC, 1);
    conv_sep_kernel<128,128><<<gb, 256>>>(x, wT + OFF_VW, bv_w, vw, CC, 0);
    dim3 gs(HW/256, 1, BB);
    conv_sep_kernel<32,256><<<gs, 128>>>(x, wT + OFF_QH, bq_h, qh, C8, 1);
    conv_sep_kernel<32,256><<<gs, 128>>>(x, wT + OFF_QW, bq_w, qw, C8, 0);
    conv_sep_kernel<32,256><<<gs, 128>>>(x, wT + OFF_KH, bk_h, kh, C8, 1);
    conv_sep_kernel<32,256><<<gs, 128>>>(x, wT + OFF_KW, bk_w, kw, C8, 0);

    // 3) attention scores
    dim3 ge(96, BB);
    eh_kernel<<<ge, 256>>>(qh, kh, eh);
    ew_kernel<<<ge, 256>>>(qw, kw, ew);

    // 4) softmax (in-place: eh/ew become a_h/a_w)
    softmax_kernel<<<(BB*HW)/8, 256>>>(eh, ew);

    // 5) attention outputs
    size_t smemO = (9216 + 96*32) * sizeof(float);   // 49152 B
    size_t smemW = (9216 + 96*33) * sizeof(float);   // 49536 B
    cudaFuncSetAttribute(outh_kernel, cudaFuncAttributeMaxDynamicSharedMemorySize, 51200);
    cudaFuncSetAttribute(outw_kernel, cudaFuncAttributeMaxDynamicSharedMemorySize, 51200);
    dim3 go(96, CC/32, BB);
    outh_kernel<<<go, 256, smemO>>>(vh, eh, oh);
    outw_kernel<<<go, 256, smemW>>>(vw, ew, ow);

    // 6) combine
    combine_kernel<<<(BB*CC*HW)/4/256, 256>>>(x, oh, ow, gamma, out);
}

// round 5
// speedup vs baseline: 2.4278x; 2.4278x over previous
#include <cuda_runtime.h>
#include <cuda_fp16.h>
#include <cstdint>

// Problem constants
#define BB 16
#define CC 256
#define C8 32
#define HH 96
#define WW 96
#define HW (HH*WW)          // 9216
#define KK 11
#define KDIM (KK*CC)        // 2816
#define NCHUNK 44           // KDIM / 64

// ---------------- scratch ----------------
#define SZ_SMALL (BB*C8*HW)
#define SZ_BIG   ((size_t)BB*CC*HW)
#define SZ_E     ((size_t)BB*HH*WW*96)
#define SZ_A     (384*KDIM)
#define SZ_XT    ((size_t)BB*HW*CC)

__device__ __half g_Ah_v[SZ_A];
__device__ __half g_Al_v[SZ_A];
__device__ __half g_Ah_h[SZ_A];
__device__ __half g_Al_h[SZ_A];
__device__ __half g_xth[SZ_XT];
__device__ __half g_xtl[SZ_XT];
__device__ float g_qh[SZ_SMALL];
__device__ float g_qw[SZ_SMALL];
__device__ float g_kh[SZ_SMALL];
__device__ float g_kw[SZ_SMALL];
__device__ float g_vh[SZ_BIG];
__device__ float g_vw[SZ_BIG];
__device__ float g_eh[SZ_E];
__device__ float g_ew[SZ_E];
__device__ float g_oh[SZ_BIG];
__device__ float g_ow[SZ_BIG];

// ---------------- warp-MMA helpers (sm_80+ PTX only; no 'a' features) ----------------
__device__ __forceinline__ uint32_t smem_u32(const void* p) {
    uint32_t a;
    asm("{ .reg .u64 t; cvta.to.shared.u64 t, %1; cvt.u32.u64 %0, t; }" : "=r"(a) : "l"(p));
    return a;
}
__device__ __forceinline__ void ldmx4(uint32_t* r, uint32_t addr) {
    asm volatile("ldmatrix.sync.aligned.m8n8.x4.shared.b16 {%0,%1,%2,%3}, [%4];"
        : "=r"(r[0]), "=r"(r[1]), "=r"(r[2]), "=r"(r[3]) : "r"(addr));
}
__device__ __forceinline__ void mma16816(float* d, const uint32_t* a, const uint32_t* b) {
    asm volatile("mma.sync.aligned.m16n8k16.row.col.f32.f16.f16.f32 "
        "{%0,%1,%2,%3}, {%4,%5,%6,%7}, {%8,%9}, {%0,%1,%2,%3};"
        : "+f"(d[0]), "+f"(d[1]), "+f"(d[2]), "+f"(d[3])
        : "r"(a[0]), "r"(a[1]), "r"(a[2]), "r"(a[3]), "r"(b[0]), "r"(b[1]));
}

// ---------------- prep: pack weights [o][k=t*256+c] fp16 hi/lo (v,q,k fused, 384 rows) ----------------
__global__ __launch_bounds__(256)
void packW_kernel(const float* __restrict__ wv, const float* __restrict__ wq,
                  const float* __restrict__ wk,
                  __half* __restrict__ Ah, __half* __restrict__ Al)
{
    int idx = blockIdx.x * 256 + threadIdx.x;
    if (idx >= 384 * KDIM) return;
    int o = idx / KDIM;
    int k = idx % KDIM;
    int t = k >> 8;
    int c = k & 255;
    float v = 0.f;
    if (o < 256)      v = wv[((size_t)o * 256 + c) * 11 + t];
    else if (o < 288) v = wq[((size_t)(o - 256) * 256 + c) * 11 + t];
    else if (o < 320) v = wk[((size_t)(o - 288) * 256 + c) * 11 + t];
    __half h = __float2half_rn(v);
    Ah[idx] = h;
    Al[idx] = __float2half_rn(v - __half2float(h));
}

// ---------------- prep: x split + transpose to [b][p][c] fp16 hi/lo ----------------
__global__ __launch_bounds__(256)
void xsplit_kernel(const float* __restrict__ x,
                   __half* __restrict__ xh, __half* __restrict__ xl)
{
    __shared__ float tile[32][33];
    const int b = blockIdx.z;
    const int c0 = blockIdx.y * 32;
    const int p0 = blockIdx.x * 32;
    const int tx = threadIdx.x & 31;
    const int ty = threadIdx.x >> 5;   // 0..7
#pragma unroll
    for (int i = 0; i < 4; i++) {
        int ci = ty + i * 8;
        tile[ci][tx] = x[((size_t)b * CC + c0 + ci) * HW + p0 + tx];
    }
    __syncthreads();
#pragma unroll
    for (int i = 0; i < 4; i++) {
        int pi = ty + i * 8;
        float v = tile[tx][pi];
        size_t o = ((size_t)b * HW + p0 + pi) * CC + c0 + tx;
        __half h = __float2half_rn(v);
        xh[o] = h;
        xl[o] = __float2half_rn(v - __half2float(h));
    }
}

// ---------------- conv GEMM via warp mma.sync, fp16-split x3, fp32 accum ----------------
// smem: Ah[128][72], Al, Bh, Bl (halves; row stride 72 = 144B -> conflict-free ldmatrix)
#define SROW 72
#define SA_BYTES (128*SROW*2)   // 18432
__global__ __launch_bounds__(256, 2)
void conv_mma_kernel(const __half* __restrict__ xh, const __half* __restrict__ xl,
                     const __half* __restrict__ Ah, const __half* __restrict__ Al,
                     const float* __restrict__ bv, const float* __restrict__ bq,
                     const float* __restrict__ bk,
                     float* __restrict__ vOut, float* __restrict__ qOut, float* __restrict__ kOut,
                     int isVert)
{
    extern __shared__ char smem[];
    __half* sAh = (__half*)(smem);
    __half* sAl = (__half*)(smem + SA_BYTES);
    __half* sBh = (__half*)(smem + 2 * SA_BYTES);
    __half* sBl = (__half*)(smem + 3 * SA_BYTES);

    const int tid = threadIdx.x;
    const int lane = tid & 31;
    const int wid = tid >> 5;
    const int p0 = blockIdx.x * 128;
    const int ot = blockIdx.y;
    const int bz = blockIdx.z;
    const int obase = ot * 128;
    const int wm = (wid & 1) * 64;
    const int wn = (wid >> 1) * 32;

    const __half* xbh = xh + (size_t)bz * HW * CC;
    const __half* xbl = xl + (size_t)bz * HW * CC;

    const uint32_t aAh = smem_u32(sAh);
    const uint32_t aAl = smem_u32(sAl);
    const uint32_t aBh = smem_u32(sBh);
    const uint32_t aBl = smem_u32(sBl);

    // ldmatrix lane address components
    const int arow = lane & 15;                        // A: rows 0-15 of m16
    const int akoff = (lane >> 4) << 3;                // A: k offset 0/8
    const int brow = (lane & 7) + ((lane >> 4) << 3);  // B: n row within n16
    const int bkoff = ((lane >> 3) & 1) << 3;          // B: k offset 0/8

    float acc[4][4][4];
#pragma unroll
    for (int a = 0; a < 4; a++)
#pragma unroll
        for (int b = 0; b < 4; b++)
#pragma unroll
            for (int c = 0; c < 4; c++) acc[a][b][c] = 0.f;

    for (int ck = 0; ck < NCHUNK; ck++) {
        const int t = ck >> 2;
        const int c0k = (ck & 3) << 6;
        const int sh = t - 5;
        const int off = isVert ? sh * WW : sh;
        const int k0 = t * 256 + c0k;

        // ---- stage A (weights) hi/lo ----
#pragma unroll
        for (int i = 0; i < 4; i++) {
            int idx = tid + i * 256;
            int r = idx >> 3, c16 = idx & 7;
            const uint4* pa = (const uint4*)(Ah + (size_t)(obase + r) * KDIM + k0) + c16;
            const uint4* pl = (const uint4*)(Al + (size_t)(obase + r) * KDIM + k0) + c16;
            uint32_t so = (uint32_t)(r * SROW * 2 + c16 * 16);
            *(uint4*)((char*)sAh + so) = *pa;
            *(uint4*)((char*)sAl + so) = *pl;
        }
        // ---- stage B (shifted x) hi/lo ----
#pragma unroll
        for (int i = 0; i < 4; i++) {
            int idx = tid + i * 256;
            int r = idx >> 3, c16 = idx & 7;
            int p = p0 + r;
            bool valid = isVert ? ((unsigned)(p + off) < (unsigned)HW)
                                : ((unsigned)(p % WW + sh) < (unsigned)WW);
            uint4 vh4 = make_uint4(0u, 0u, 0u, 0u);
            uint4 vl4 = make_uint4(0u, 0u, 0u, 0u);
            if (valid) {
                size_t go = (size_t)(p + off) * CC + c0k + c16 * 8;
                vh4 = *(const uint4*)(xbh + go);
                vl4 = *(const uint4*)(xbl + go);
            }
            uint32_t so = (uint32_t)(r * SROW * 2 + c16 * 16);
            *(uint4*)((char*)sBh + so) = vh4;
            *(uint4*)((char*)sBl + so) = vl4;
        }
        __syncthreads();

        // ---- compute: 4 x k16 ----
#pragma unroll
        for (int k16 = 0; k16 < 4; k16++) {
            const int kb = k16 * 16;
            uint32_t bh[2][4], bl[2][4];
#pragma unroll
            for (int ng = 0; ng < 2; ng++) {
                uint32_t boff = (uint32_t)(((wn + ng * 16 + brow) * SROW + kb + bkoff) * 2);
                ldmx4(bh[ng], aBh + boff);
                ldmx4(bl[ng], aBl + boff);
            }
#pragma unroll
            for (int mi = 0; mi < 4; mi++) {
                uint32_t aoff = (uint32_t)(((wm + mi * 16 + arow) * SROW + kb + akoff) * 2);
                uint32_t ah[4], al[4];
                ldmx4(ah, aAh + aoff);
                ldmx4(al, aAl + aoff);
#pragma unroll
                for (int ni = 0; ni < 4; ni++) {
                    const uint32_t* bfh = &bh[ni >> 1][(ni & 1) * 2];
                    const uint32_t* bfl = &bl[ni >> 1][(ni & 1) * 2];
                    mma16816(acc[mi][ni], ah, bfh);
                    mma16816(acc[mi][ni], ah, bfl);
                    mma16816(acc[mi][ni], al, bfh);
                }
            }
        }
        __syncthreads();
    }

    // ---- epilogue: write v/q/k with bias ----
#pragma unroll
    for (int mi = 0; mi < 4; mi++) {
#pragma unroll
        for (int half_ = 0; half_ < 2; half_++) {
            int rr = wm + mi * 16 + (lane >> 2) + half_ * 8;   // local row in [0,128)
            float bias = 0.f;
            float* dst = nullptr;
            if (ot < 2) {
                int o = obase + rr;
                bias = bv[o];
                dst = vOut + ((size_t)bz * CC + o) * HW;
            } else if (rr < 32) {
                bias = bq[rr];
                dst = qOut + ((size_t)bz * C8 + rr) * HW;
            } else if (rr < 64) {
                bias = bk[rr - 32];
                dst = kOut + ((size_t)bz * C8 + rr - 32) * HW;
            }
            if (dst) {
#pragma unroll
                for (int ni = 0; ni < 4; ni++) {
                    int col = p0 + wn + ni * 8 + (lane & 3) * 2;
                    float2 v2;
                    v2.x = acc[mi][ni][half_ * 2 + 0] + bias;
                    v2.y = acc[mi][ni][half_ * 2 + 1] + bias;
                    *(float2*)(dst + col) = v2;
                }
            }
        }
    }
}

// ---------------- e_h: per (b,w), E[h][H] = sum_c Q[c][h] K[c][H] ----------------
__global__ __launch_bounds__(256)
void eh_kernel(const float* __restrict__ qh, const float* __restrict__ kh,
               float* __restrict__ eh)
{
    const int w = blockIdx.x;
    const int b = blockIdx.y;
    __shared__ float Qs[C8][HH];
    __shared__ float Ks[C8][HH];
    const int tid = threadIdx.x;
    const float* qb = qh + (size_t)b * C8 * HW + w;
    const float* kb = kh + (size_t)b * C8 * HW + w;
    for (int l = tid; l < C8 * HH; l += 256) {
        int c = l / HH, h = l % HH;
        Qs[c][h] = qb[(size_t)c * HW + h * WW];
        Ks[c][h] = kb[(size_t)c * HW + h * WW];
    }
    __syncthreads();
    const int h0 = (tid / 16) * 6;
    const int H0 = (tid % 16) * 6;
    float acc[6][6];
#pragma unroll
    for (int i = 0; i < 6; i++)
#pragma unroll
        for (int j = 0; j < 6; j++) acc[i][j] = 0.f;
    for (int c = 0; c < C8; ++c) {
        float q[6], k[6];
#pragma unroll
        for (int i = 0; i < 6; i++) q[i] = Qs[c][h0 + i];
#pragma unroll
        for (int j = 0; j < 6; j++) k[j] = Ks[c][H0 + j];
#pragma unroll
        for (int i = 0; i < 6; i++)
#pragma unroll
            for (int j = 0; j < 6; j++) acc[i][j] += q[i] * k[j];
    }
    float* ep = eh + ((size_t)b * WW + w) * HH * 96;
#pragma unroll
    for (int i = 0; i < 6; i++)
#pragma unroll
        for (int j = 0; j < 6; j++)
            ep[(h0 + i) * 96 + H0 + j] = acc[i][j];
}

// ---------------- e_w ----------------
__global__ __launch_bounds__(256)
void ew_kernel(const float* __restrict__ qw, const float* __restrict__ kw,
               float* __restrict__ ew)
{
    const int h = blockIdx.x;
    const int b = blockIdx.y;
    __shared__ float Qs[C8][WW];
    __shared__ float Ks[C8][WW];
    const int tid = threadIdx.x;
    const float* qb = qw + (size_t)b * C8 * HW + (size_t)h * WW;
    const float* kb = kw + (size_t)b * C8 * HW + (size_t)h * WW;
    for (int l = tid; l < C8 * WW; l += 256) {
        int c = l / WW, w = l % WW;
        Qs[c][w] = qb[(size_t)c * HW + w];
        Ks[c][w] = kb[(size_t)c * HW + w];
    }
    __syncthreads();
    const int w0 = (tid / 16) * 6;
    const int W0 = (tid % 16) * 6;
    float acc[6][6];
#pragma unroll
    for (int i = 0; i < 6; i++)
#pragma unroll
        for (int j = 0; j < 6; j++) acc[i][j] = 0.f;
    for (int c = 0; c < C8; ++c) {
        float q[6], k[6];
#pragma unroll
        for (int i = 0; i < 6; i++) q[i] = Qs[c][w0 + i];
#pragma unroll
        for (int j = 0; j < 6; j++) k[j] = Ks[c][W0 + j];
#pragma unroll
        for (int i = 0; i < 6; i++)
#pragma unroll
            for (int j = 0; j < 6; j++) acc[i][j] += q[i] * k[j];
    }
    float* ep = ew + ((size_t)b * HH + h) * WW * 96;
#pragma unroll
    for (int i = 0; i < 6; i++)
#pragma unroll
        for (int j = 0; j < 6; j++)
            ep[(w0 + i) * 96 + W0 + j] = acc[i][j];
}

// ---------------- softmax over concat(e_h row, e_w row), in-place ----------------
__global__ __launch_bounds__(256)
void softmax_kernel(float* __restrict__ eh, float* __restrict__ ew)
{
    const int warp = threadIdx.x / 32;
    const int lane = threadIdx.x % 32;
    const int r = blockIdx.x * 8 + warp;
    const int b = r / HW;
    const int rem = r % HW;
    const int h = rem / WW;
    const int w = rem % WW;
    float* ehp = eh + (((size_t)b * WW + w) * HH + h) * 96;
    float* ewp = ew + (((size_t)b * HH + h) * WW + w) * 96;

    float vh[3], vw[3];
    float m = -3.0e38f;
#pragma unroll
    for (int j = 0; j < 3; j++) {
        int H = lane + 32 * j;
        float a = (H == h) ? -3.0e38f : ehp[H];
        float c = ewp[H];
        vh[j] = a; vw[j] = c;
        m = fmaxf(m, fmaxf(a, c));
    }
#pragma unroll
    for (int s = 16; s > 0; s >>= 1)
        m = fmaxf(m, __shfl_xor_sync(0xffffffffu, m, s));
    float sum = 0.f;
#pragma unroll
    for (int j = 0; j < 3; j++) {
        vh[j] = __expf(vh[j] - m);
        vw[j] = __expf(vw[j] - m);
        sum += vh[j] + vw[j];
    }
#pragma unroll
    for (int s = 16; s > 0; s >>= 1)
        sum += __shfl_xor_sync(0xffffffffu, sum, s);
    float inv = 1.0f / sum;
#pragma unroll
    for (int j = 0; j < 3; j++) {
        int H = lane + 32 * j;
        ehp[H] = vh[j] * inv;
        ewp[H] = vw[j] * inv;
    }
}

// ---------------- out_h ----------------
__global__ __launch_bounds__(256)
void outh_kernel(const float* __restrict__ vh, const float* __restrict__ ah,
                 float* __restrict__ oh)
{
    extern __shared__ float sm[];
    float* As = sm;
    float* Vs = sm + 96 * 96;
    const int w = blockIdx.x;
    const int c0 = blockIdx.y * 32;
    const int b = blockIdx.z;
    const int tid = threadIdx.x;

    const float* ab = ah + ((size_t)b * WW + w) * 9216;
    for (int l = tid; l < 9216; l += 256) As[l] = ab[l];
    for (int l = tid; l < 96 * 32; l += 256) {
        int Hc = l / 32, c = l % 32;
        Vs[Hc * 32 + c] = vh[((size_t)b * CC + c0 + c) * HW + Hc * WW + w];
    }
    __syncthreads();

    const int c = tid % 32;
    const int hg = tid / 32;
    float acc[12];
#pragma unroll
    for (int k = 0; k < 12; k++) acc[k] = 0.f;
    for (int Hc = 0; Hc < 96; ++Hc) {
        float v = Vs[Hc * 32 + c];
#pragma unroll
        for (int k = 0; k < 12; k++)
            acc[k] += v * As[(hg * 12 + k) * 96 + Hc];
    }
#pragma unroll
    for (int k = 0; k < 12; k++) {
        int h = hg * 12 + k;
        oh[((size_t)b * CC + c0 + c) * HW + h * WW + w] = acc[k];
    }
}

// ---------------- out_w ----------------
__global__ __launch_bounds__(256)
void outw_kernel(const float* __restrict__ vw, const float* __restrict__ aw,
                 float* __restrict__ ow)
{
    extern __shared__ float sm[];
    float* As = sm;
    float* Vs = sm + 96 * 96;
    const int h = blockIdx.x;
    const int c0 = blockIdx.y * 32;
    const int b = blockIdx.z;
    const int tid = threadIdx.x;

    const float* ab = aw + ((size_t)b * HH + h) * 9216;
    for (int l = tid; l < 9216; l += 256) As[l] = ab[l];
    for (int l = tid; l < 96 * 32; l += 256) {
        int c = l / 96, Wc = l % 96;
        Vs[Wc * 33 + c] = vw[((size_t)b * CC + c0 + c) * HW + (size_t)h * WW + Wc];
    }
    __syncthreads();

    const int c = tid % 32;
    const int wg = tid / 32;
    float acc[12];
#pragma unroll
    for (int k = 0; k < 12; k++) acc[k] = 0.f;
    for (int Wc = 0; Wc < 96; ++Wc) {
        float v = Vs[Wc * 33 + c];
#pragma unroll
        for (int k = 0; k < 12; k++)
            acc[k] += v * As[(wg * 12 + k) * 96 + Wc];
    }
#pragma unroll
    for (int k = 0; k < 12; k++) {
        int w = wg * 12 + k;
        ow[((size_t)b * CC + c0 + c) * HW + (size_t)h * WW + w] = acc[k];
    }
}

// ---------------- final combine ----------------
__global__ __launch_bounds__(256)
void combine_kernel(const float* __restrict__ x, const float* __restrict__ oh,
                    const float* __restrict__ ow, const float* __restrict__ gamma,
                    float* __restrict__ out)
{
    size_t i = (size_t)blockIdx.x * 256 + threadIdx.x;
    const float4* x4 = (const float4*)x;
    const float4* a4 = (const float4*)oh;
    const float4* b4 = (const float4*)ow;
    float4* o4 = (float4*)out;
    float g = gamma[0];
    float4 xa = x4[i], aa = a4[i], bb = b4[i];
    float4 r;
    r.x = g * (aa.x + bb.x) + xa.x;
    r.y = g * (aa.y + bb.y) + xa.y;
    r.z = g * (aa.z + bb.z) + xa.z;
    r.w = g * (aa.w + bb.w) + xa.w;
    o4[i] = r;
}

// ---------------- launch ----------------
extern "C" void kernel_launch(void* const* d_in, const int* in_sizes, int n_in,
                              void* d_out, int out_size)
{
    const float* x    = (const float*)d_in[0];
    const float* wq_h = (const float*)d_in[1];
    const float* bq_h = (const float*)d_in[2];
    const float* wq_w = (const float*)d_in[3];
    const float* bq_w = (const float*)d_in[4];
    const float* wk_h = (const float*)d_in[5];
    const float* bk_h = (const float*)d_in[6];
    const float* wk_w = (const float*)d_in[7];
    const float* bk_w = (const float*)d_in[8];
    const float* wv_h = (const float*)d_in[9];
    const float* bv_h = (const float*)d_in[10];
    const float* wv_w = (const float*)d_in[11];
    const float* bv_w = (const float*)d_in[12];
    const float* gamma= (const float*)d_in[13];
    float* out = (float*)d_out;

    __half *Ahv, *Alv, *Ahh, *Alh, *xth, *xtl;
    float *qh, *qw, *kh, *kw, *vh, *vw, *eh, *ew, *oh, *ow;
    cudaGetSymbolAddress((void**)&Ahv, g_Ah_v);
    cudaGetSymbolAddress((void**)&Alv, g_Al_v);
    cudaGetSymbolAddress((void**)&Ahh, g_Ah_h);
    cudaGetSymbolAddress((void**)&Alh, g_Al_h);
    cudaGetSymbolAddress((void**)&xth, g_xth);
    cudaGetSymbolAddress((void**)&xtl, g_xtl);
    cudaGetSymbolAddress((void**)&qh, g_qh);
    cudaGetSymbolAddress((void**)&qw, g_qw);
    cudaGetSymbolAddress((void**)&kh, g_kh);
    cudaGetSymbolAddress((void**)&kw, g_kw);
    cudaGetSymbolAddress((void**)&vh, g_vh);
    cudaGetSymbolAddress((void**)&vw, g_vw);
    cudaGetSymbolAddress((void**)&eh, g_eh);
    cudaGetSymbolAddress((void**)&ew, g_ew);
    cudaGetSymbolAddress((void**)&oh, g_oh);
    cudaGetSymbolAddress((void**)&ow, g_ow);

    // 1) prep
    packW_kernel<<<(384 * KDIM + 255) / 256, 256>>>(wv_h, wq_h, wk_h, Ahv, Alv);
    packW_kernel<<<(384 * KDIM + 255) / 256, 256>>>(wv_w, wq_w, wk_w, Ahh, Alh);
    dim3 gx(HW / 32, CC / 32, BB);
    xsplit_kernel<<<gx, 256>>>(x, xth, xtl);

    // 2) fused warp-MMA conv GEMMs (v,q,k per direction)
    cudaFuncSetAttribute(conv_mma_kernel, cudaFuncAttributeMaxDynamicSharedMemorySize, 4 * SA_BYTES);
    dim3 gc(HW / 128, 3, BB);
    conv_mma_kernel<<<gc, 256, 4 * SA_BYTES>>>(xth, xtl, Ahv, Alv, bv_h, bq_h, bk_h, vh, qh, kh, 1);
    conv_mma_kernel<<<gc, 256, 4 * SA_BYTES>>>(xth, xtl, Ahh, Alh, bv_w, bq_w, bk_w, vw, qw, kw, 0);

    // 3) attention scores
    dim3 ge(96, BB);
    eh_kernel<<<ge, 256>>>(qh, kh, eh);
    ew_kernel<<<ge, 256>>>(qw, kw, ew);

    // 4) softmax
    softmax_kernel<<<(BB * HW) / 8, 256>>>(eh, ew);

    // 5) attention outputs
    size_t smemO = (9216 + 96 * 32) * sizeof(float);
    size_t smemW = (9216 + 96 * 33) * sizeof(float);
    cudaFuncSetAttribute(outh_kernel, cudaFuncAttributeMaxDynamicSharedMemorySize, 51200);
    cudaFuncSetAttribute(outw_kernel, cudaFuncAttributeMaxDynamicSharedMemorySize, 51200);
    dim3 go(96, CC / 32, BB);
    outh_kernel<<<go, 256, smemO>>>(vh, eh, oh);
    outw_kernel<<<go, 256, smemW>>>(vw, ew, ow);

    // 6) combine
    combine_kernel<<<(BB * CC * HW) / 4 / 256, 256>>>(x, oh, ow, gamma, out);
}

// round 11
// speedup vs baseline: 4.2264x; 1.7409x over previous
#include <cuda_runtime.h>
#include <cuda_fp16.h>
#include <cstdint>

// Problem constants
#define BB 16
#define CC 256
#define C8 32
#define HH 96
#define WW 96
#define HW (HH*WW)          // 9216
#define KK 11
#define KDIM (KK*CC)        // 2816
#define NCHUNK 44           // KDIM / 64

// ---------------- scratch ----------------
#define SZ_SMALL (BB*C8*HW)
#define SZ_BIG   ((size_t)BB*CC*HW)
#define SZ_E     ((size_t)BB*HH*WW*96)
#define SZ_A     (384*KDIM)
#define SZ_XT    ((size_t)BB*HW*CC)

__device__ __half g_Awh_v[SZ_A];   // fp16(w), vertical dir (v,q,k fused rows)
__device__ __half g_Awl_v[SZ_A];   // fp16(w - hi)
__device__ __half g_Awh_h[SZ_A];
__device__ __half g_Awl_h[SZ_A];
__device__ __half g_xth[SZ_XT];
__device__ __half g_xtl[SZ_XT];
__device__ float g_qh[SZ_SMALL];
__device__ float g_qw[SZ_SMALL];
__device__ float g_kh[SZ_SMALL];
__device__ float g_kw[SZ_SMALL];
__device__ float g_vh[SZ_BIG];
__device__ float g_vw[SZ_BIG];
__device__ float g_eh[SZ_E];
__device__ float g_ew[SZ_E];
__device__ float g_oh[SZ_BIG];
__device__ float g_ow[SZ_BIG];

// ---------------- warp-MMA helpers (sm_80+ PTX only) ----------------
__device__ __forceinline__ uint32_t smem_u32(const void* p) {
    uint32_t a;
    asm("{ .reg .u64 t; cvta.to.shared.u64 t, %1; cvt.u32.u64 %0, t; }" : "=r"(a) : "l"(p));
    return a;
}
__device__ __forceinline__ void ldmx4(uint32_t* r, uint32_t addr) {
    asm volatile("ldmatrix.sync.aligned.m8n8.x4.shared.b16 {%0,%1,%2,%3}, [%4];"
        : "=r"(r[0]), "=r"(r[1]), "=r"(r[2]), "=r"(r[3]) : "r"(addr));
}
__device__ __forceinline__ void mma16816(float* d, const uint32_t* a, const uint32_t* b) {
    asm volatile("mma.sync.aligned.m16n8k16.row.col.f32.f16.f16.f32 "
        "{%0,%1,%2,%3}, {%4,%5,%6,%7}, {%8,%9}, {%0,%1,%2,%3};"
        : "+f"(d[0]), "+f"(d[1]), "+f"(d[2]), "+f"(d[3])
        : "r"(a[0]), "r"(a[1]), "r"(a[2]), "r"(a[3]), "r"(b[0]), "r"(b[1]));
}
#define CPA16(dst, src) asm volatile("cp.async.cg.shared.global [%0], [%1], 16;" :: "r"(dst), "l"(src))
#define CPA_COMMIT() asm volatile("cp.async.commit_group;" ::: "memory")
#define CPA_WAIT1()  asm volatile("cp.async.wait_group 1;" ::: "memory")

// ---------------- prep: pack weights [o][k=t*256+c] fp16 hi/lo (v,q,k fused, 384 rows) ----------------
__global__ __launch_bounds__(256)
void packW_kernel(const float* __restrict__ wv, const float* __restrict__ wq,
                  const float* __restrict__ wk,
                  __half* __restrict__ Awh, __half* __restrict__ Awl)
{
    int idx = blockIdx.x * 256 + threadIdx.x;
    if (idx >= 384 * KDIM) return;
    int o = idx / KDIM;
    int k = idx % KDIM;
    int t = k >> 8;
    int c = k & 255;
    float v = 0.f;
    if (o < 256)      v = wv[((size_t)o * 256 + c) * 11 + t];
    else if (o < 288) v = wq[((size_t)(o - 256) * 256 + c) * 11 + t];
    else if (o < 320) v = wk[((size_t)(o - 288) * 256 + c) * 11 + t];
    __half h = __float2half_rn(v);
    Awh[idx] = h;
    Awl[idx] = __float2half_rn(v - __half2float(h));
}

// ---------------- prep: x split + transpose to [b][p][c] fp16 hi/lo ----------------
__global__ __launch_bounds__(256)
void xsplit_kernel(const float* __restrict__ x,
                   __half* __restrict__ xh, __half* __restrict__ xl)
{
    __shared__ float tile[32][33];
    const int b = blockIdx.z;
    const int c0 = blockIdx.y * 32;
    const int p0 = blockIdx.x * 32;
    const int tx = threadIdx.x & 31;
    const int ty = threadIdx.x >> 5;   // 0..7
#pragma unroll
    for (int i = 0; i < 4; i++) {
        int ci = ty + i * 8;
        tile[ci][tx] = x[((size_t)b * CC + c0 + ci) * HW + p0 + tx];
    }
    __syncthreads();
#pragma unroll
    for (int i = 0; i < 4; i++) {
        int pi = ty + i * 8;
        float v = tile[tx][pi];
        size_t o = ((size_t)b * HW + p0 + pi) * CC + c0 + tx;
        __half h = __float2half_rn(v);
        xh[o] = h;
        xl[o] = __float2half_rn(v - __half2float(h));
    }
}

#define SROW 72
#define ARR_B128 (128*SROW*2)   // 18432 (128-row array)
#define ARR_A64  (64*SROW*2)    // 9216  (64-row array)

// ---------------- V conv: M=256 (2 tiles), 1 MMA (w fp16 x xh fp16), cp.async 2-stage ----------------
// per stage: A[128][72] + Bh[128][72] = 36864 B; 2 stages = 73728
#define STG_V (2*ARR_B128)
__global__ __launch_bounds__(256, 2)
void conv_v_kernel(const __half* __restrict__ xh,
                   const __half* __restrict__ Awh,
                   const float* __restrict__ bv,
                   float* __restrict__ vOut, int isVert)
{
    extern __shared__ char smem[];
    const uint32_t sb = smem_u32(smem);
    const int tid = threadIdx.x;
    const int lane = tid & 31;
    const int wid = tid >> 5;
    const int p0 = blockIdx.x * 128;
    const int obase = blockIdx.y * 128;   // 0 or 128 (v rows)
    const int bz = blockIdx.z;
    const int wm = (wid & 1) * 64;
    const int wn = (wid >> 1) * 32;

    const __half* xbh = xh + (size_t)bz * HW * CC;

    const int arow = lane & 15;
    const int akoff = (lane >> 4) << 3;
    const int brow = (lane & 7) + ((lane >> 4) << 3);
    const int bkoff = ((lane >> 3) & 1) << 3;

    auto stage_chunk = [&](int ck, int s) {
        const int t = ck >> 2;
        const int c0k = (ck & 3) << 6;
        const int sh = t - 5;
        const int off = isVert ? sh * WW : sh;
        const int k0 = t * 256 + c0k;
        const uint32_t sA = sb + (uint32_t)s * STG_V;
        const uint32_t sB = sA + ARR_B128;
#pragma unroll
        for (int i = 0; i < 4; i++) {
            int idx = tid + i * 256;
            int r = idx >> 3, c16 = idx & 7;
            uint32_t so = (uint32_t)(r * (SROW * 2) + c16 * 16);
            CPA16(sA + so, Awh + (size_t)(obase + r) * KDIM + k0 + c16 * 8);
        }
#pragma unroll
        for (int i = 0; i < 4; i++) {
            int idx = tid + i * 256;
            int r = idx >> 3, c16 = idx & 7;
            int p = p0 + r;
            bool valid = isVert ? ((unsigned)(p + off) < (unsigned)HW)
                                : ((unsigned)(p % WW + sh) < (unsigned)WW);
            uint32_t so = (uint32_t)(r * (SROW * 2) + c16 * 16);
            if (valid) {
                size_t go = (size_t)(p + off) * CC + c0k + c16 * 8;
                CPA16(sB + so, xbh + go);
            } else {
                *(uint4*)(smem + (size_t)s * STG_V + ARR_B128 + so) = make_uint4(0u, 0u, 0u, 0u);
            }
        }
        CPA_COMMIT();
    };

    float acc[4][4][4];
#pragma unroll
    for (int a = 0; a < 4; a++)
#pragma unroll
        for (int b = 0; b < 4; b++)
#pragma unroll
            for (int c = 0; c < 4; c++) acc[a][b][c] = 0.f;

    stage_chunk(0, 0);
    stage_chunk(1, 1);

    for (int ck = 0; ck < NCHUNK; ck++) {
        const int s = ck & 1;
        CPA_WAIT1();
        __syncthreads();
        const uint32_t sA = sb + (uint32_t)s * STG_V;
        const uint32_t sB = sA + ARR_B128;

#pragma unroll
        for (int k16 = 0; k16 < 4; k16++) {
            const int kb = k16 * 16;
            uint32_t bh[2][4];
#pragma unroll
            for (int ng = 0; ng < 2; ng++) {
                uint32_t boff = (uint32_t)(((wn + ng * 16 + brow) * SROW + kb + bkoff) * 2);
                ldmx4(bh[ng], sB + boff);
            }
#pragma unroll
            for (int mi = 0; mi < 4; mi++) {
                uint32_t aoff = (uint32_t)(((wm + mi * 16 + arow) * SROW + kb + akoff) * 2);
                uint32_t ah[4];
                ldmx4(ah, sA + aoff);
#pragma unroll
                for (int ni = 0; ni < 4; ni++)
                    mma16816(acc[mi][ni], ah, &bh[ni >> 1][(ni & 1) * 2]);
            }
        }
        __syncthreads();
        if (ck + 2 < NCHUNK) stage_chunk(ck + 2, s);
    }

#pragma unroll
    for (int mi = 0; mi < 4; mi++) {
#pragma unroll
        for (int half_ = 0; half_ < 2; half_++) {
            int o = obase + wm + mi * 16 + (lane >> 2) + half_ * 8;
            float bias = bv[o];
            float* dst = vOut + ((size_t)bz * CC + o) * HW;
#pragma unroll
            for (int ni = 0; ni < 4; ni++) {
                int col = p0 + wn + ni * 8 + (lane & 3) * 2;
                float2 v2;
                v2.x = acc[mi][ni][half_ * 2 + 0] + bias;
                v2.y = acc[mi][ni][half_ * 2 + 1] + bias;
                *(float2*)(dst + col) = v2;
            }
        }
    }
}

// ---------------- QK conv: M=64 (q 0-31, k 32-63), 3 MMAs (precision-critical path) ----------------
// per stage: Ah[64][72] + Al[64][72] + Bh[128][72] + Bl[128][72] = 55296; 2 stages = 110592
#define STG_QK (2*ARR_A64 + 2*ARR_B128)
__global__ __launch_bounds__(256, 2)
void conv_qk_kernel(const __half* __restrict__ xh, const __half* __restrict__ xl,
                    const __half* __restrict__ Awh, const __half* __restrict__ Awl,
                    const float* __restrict__ bq, const float* __restrict__ bk,
                    float* __restrict__ qOut, float* __restrict__ kOut, int isVert)
{
    extern __shared__ char smem[];
    const uint32_t sb = smem_u32(smem);
    const int tid = threadIdx.x;
    const int lane = tid & 31;
    const int wid = tid >> 5;
    const int p0 = blockIdx.x * 128;
    const int bz = blockIdx.z;
    const int wn16 = wid * 16;     // 8 warps x n16 = 128 N

    const __half* xbh = xh + (size_t)bz * HW * CC;
    const __half* xbl = xl + (size_t)bz * HW * CC;

    const int arow = lane & 15;
    const int akoff = (lane >> 4) << 3;
    const int brow = (lane & 7) + ((lane >> 4) << 3);
    const int bkoff = ((lane >> 3) & 1) << 3;

    auto stage_chunk = [&](int ck, int s) {
        const int t = ck >> 2;
        const int c0k = (ck & 3) << 6;
        const int sh = t - 5;
        const int off = isVert ? sh * WW : sh;
        const int k0 = t * 256 + c0k;
        const uint32_t sAh = sb + (uint32_t)s * STG_QK;
        const uint32_t sAl = sAh + ARR_A64;
        const uint32_t sBh = sAl + ARR_A64;
        const uint32_t sBl = sBh + ARR_B128;
        // A hi/lo: 64 rows (global rows 256..319 = q,k), 512 uint4 each
#pragma unroll
        for (int i = 0; i < 2; i++) {
            int idx = tid + i * 256;
            int r = idx >> 3, c16 = idx & 7;
            uint32_t so = (uint32_t)(r * (SROW * 2) + c16 * 16);
            size_t go = (size_t)(256 + r) * KDIM + k0 + c16 * 8;
            CPA16(sAh + so, Awh + go);
            CPA16(sAl + so, Awl + go);
        }
        // B hi/lo: 128 rows
#pragma unroll
        for (int i = 0; i < 4; i++) {
            int idx = tid + i * 256;
            int r = idx >> 3, c16 = idx & 7;
            int p = p0 + r;
            bool valid = isVert ? ((unsigned)(p + off) < (unsigned)HW)
                                : ((unsigned)(p % WW + sh) < (unsigned)WW);
            uint32_t so = (uint32_t)(r * (SROW * 2) + c16 * 16);
            if (valid) {
                size_t go = (size_t)(p + off) * CC + c0k + c16 * 8;
                CPA16(sBh + so, xbh + go);
                CPA16(sBl + so, xbl + go);
            } else {
                uint4 z = make_uint4(0u, 0u, 0u, 0u);
                *(uint4*)(smem + (size_t)s * STG_QK + 2 * ARR_A64 + so) = z;
                *(uint4*)(smem + (size_t)s * STG_QK + 2 * ARR_A64 + ARR_B128 + so) = z;
            }
        }
        CPA_COMMIT();
    };

    float acc[4][2][4];
#pragma unroll
    for (int a = 0; a < 4; a++)
#pragma unroll
        for (int b = 0; b < 2; b++)
#pragma unroll
            for (int c = 0; c < 4; c++) acc[a][b][c] = 0.f;

    stage_chunk(0, 0);
    stage_chunk(1, 1);

    for (int ck = 0; ck < NCHUNK; ck++) {
        const int s = ck & 1;
        CPA_WAIT1();
        __syncthreads();
        const uint32_t sAh = sb + (uint32_t)s * STG_QK;
        const uint32_t sAl = sAh + ARR_A64;
        const uint32_t sBh = sAl + ARR_A64;
        const uint32_t sBl = sBh + ARR_B128;

#pragma unroll
        for (int k16 = 0; k16 < 4; k16++) {
            const int kb = k16 * 16;
            uint32_t bh[4], bl[4];
            uint32_t boff = (uint32_t)(((wn16 + brow) * SROW + kb + bkoff) * 2);
            ldmx4(bh, sBh + boff);
            ldmx4(bl, sBl + boff);
#pragma unroll
            for (int mi = 0; mi < 4; mi++) {
                uint32_t aoff = (uint32_t)(((mi * 16 + arow) * SROW + kb + akoff) * 2);
                uint32_t ah[4], al[4];
                ldmx4(ah, sAh + aoff);
                ldmx4(al, sAl + aoff);
#pragma unroll
                for (int ni = 0; ni < 2; ni++) {
                    mma16816(acc[mi][ni], ah, &bh[ni * 2]);
                    mma16816(acc[mi][ni], ah, &bl[ni * 2]);
                    mma16816(acc[mi][ni], al, &bh[ni * 2]);
                }
            }
        }
        __syncthreads();
        if (ck + 2 < NCHUNK) stage_chunk(ck + 2, s);
    }

#pragma unroll
    for (int mi = 0; mi < 4; mi++) {
#pragma unroll
        for (int half_ = 0; half_ < 2; half_++) {
            int rr = mi * 16 + (lane >> 2) + half_ * 8;   // [0,64): q then k
            float bias;
            float* dst;
            if (rr < 32) {
                bias = bq[rr];
                dst = qOut + ((size_t)bz * C8 + rr) * HW;
            } else {
                bias = bk[rr - 32];
                dst = kOut + ((size_t)bz * C8 + rr - 32) * HW;
            }
#pragma unroll
            for (int ni = 0; ni < 2; ni++) {
                int col = p0 + wn16 + ni * 8 + (lane & 3) * 2;
                float2 v2;
                v2.x = acc[mi][ni][half_ * 2 + 0] + bias;
                v2.y = acc[mi][ni][half_ * 2 + 1] + bias;
                *(float2*)(dst + col) = v2;
            }
        }
    }
}

// ---------------- e_h: per (b,w), E[h][H] = sum_c Q[c][h] K[c][H] ----------------
__global__ __launch_bounds__(256)
void eh_kernel(const float* __restrict__ qh, const float* __restrict__ kh,
               float* __restrict__ eh)
{
    const int w = blockIdx.x;
    const int b = blockIdx.y;
    __shared__ float Qs[C8][HH];
    __shared__ float Ks[C8][HH];
    const int tid = threadIdx.x;
    const float* qb = qh + (size_t)b * C8 * HW + w;
    const float* kb = kh + (size_t)b * C8 * HW + w;
    for (int l = tid; l < C8 * HH; l += 256) {
        int c = l / HH, h = l % HH;
        Qs[c][h] = qb[(size_t)c * HW + h * WW];
        Ks[c][h] = kb[(size_t)c * HW + h * WW];
    }
    __syncthreads();
    const int h0 = (tid / 16) * 6;
    const int H0 = (tid % 16) * 6;
    float acc[6][6];
#pragma unroll
    for (int i = 0; i < 6; i++)
#pragma unroll
        for (int j = 0; j < 6; j++) acc[i][j] = 0.f;
    for (int c = 0; c < C8; ++c) {
        float q[6], k[6];
#pragma unroll
        for (int i = 0; i < 6; i++) q[i] = Qs[c][h0 + i];
#pragma unroll
        for (int j = 0; j < 6; j++) k[j] = Ks[c][H0 + j];
#pragma unroll
        for (int i = 0; i < 6; i++)
#pragma unroll
            for (int j = 0; j < 6; j++) acc[i][j] += q[i] * k[j];
    }
    float* ep = eh + ((size_t)b * WW + w) * HH * 96;
#pragma unroll
    for (int i = 0; i < 6; i++)
#pragma unroll
        for (int j = 0; j < 6; j++)
            ep[(h0 + i) * 96 + H0 + j] = acc[i][j];
}

// ---------------- e_w ----------------
__global__ __launch_bounds__(256)
void ew_kernel(const float* __restrict__ qw, const float* __restrict__ kw,
               float* __restrict__ ew)
{
    const int h = blockIdx.x;
    const int b = blockIdx.y;
    __shared__ float Qs[C8][WW];
    __shared__ float Ks[C8][WW];
    const int tid = threadIdx.x;
    const float* qb = qw + (size_t)b * C8 * HW + (size_t)h * WW;
    const float* kb = kw + (size_t)b * C8 * HW + (size_t)h * WW;
    for (int l = tid; l < C8 * WW; l += 256) {
        int c = l / WW, w = l % WW;
        Qs[c][w] = qb[(size_t)c * HW + w];
        Ks[c][w] = kb[(size_t)c * HW + w];
    }
    __syncthreads();
    const int w0 = (tid / 16) * 6;
    const int W0 = (tid % 16) * 6;
    float acc[6][6];
#pragma unroll
    for (int i = 0; i < 6; i++)
#pragma unroll
        for (int j = 0; j < 6; j++) acc[i][j] = 0.f;
    for (int c = 0; c < C8; ++c) {
        float q[6], k[6];
#pragma unroll
        for (int i = 0; i < 6; i++) q[i] = Qs[c][w0 + i];
#pragma unroll
        for (int j = 0; j < 6; j++) k[j] = Ks[c][W0 + j];
#pragma unroll
        for (int i = 0; i < 6; i++)
#pragma unroll
            for (int j = 0; j < 6; j++) acc[i][j] += q[i] * k[j];
    }
    float* ep = ew + ((size_t)b * HH + h) * WW * 96;
#pragma unroll
    for (int i = 0; i < 6; i++)
#pragma unroll
        for (int j = 0; j < 6; j++)
            ep[(w0 + i) * 96 + W0 + j] = acc[i][j];
}

// ---------------- softmax over concat(e_h row, e_w row), in-place ----------------
__global__ __launch_bounds__(256)
void softmax_kernel(float* __restrict__ eh, float* __restrict__ ew)
{
    const int warp = threadIdx.x / 32;
    const int lane = threadIdx.x % 32;
    const int r = blockIdx.x * 8 + warp;
    const int b = r / HW;
    const int rem = r % HW;
    const int h = rem / WW;
    const int w = rem % WW;
    float* ehp = eh + (((size_t)b * WW + w) * HH + h) * 96;
    float* ewp = ew + (((size_t)b * HH + h) * WW + w) * 96;

    float vh[3], vw[3];
    float m = -3.0e38f;
#pragma unroll
    for (int j = 0; j < 3; j++) {
        int H = lane + 32 * j;
        float a = (H == h) ? -3.0e38f : ehp[H];
        float c = ewp[H];
        vh[j] = a; vw[j] = c;
        m = fmaxf(m, fmaxf(a, c));
    }
#pragma unroll
    for (int s = 16; s > 0; s >>= 1)
        m = fmaxf(m, __shfl_xor_sync(0xffffffffu, m, s));
    float sum = 0.f;
#pragma unroll
    for (int j = 0; j < 3; j++) {
        vh[j] = __expf(vh[j] - m);
        vw[j] = __expf(vw[j] - m);
        sum += vh[j] + vw[j];
    }
#pragma unroll
    for (int s = 16; s > 0; s >>= 1)
        sum += __shfl_xor_sync(0xffffffffu, sum, s);
    float inv = 1.0f / sum;
#pragma unroll
    for (int j = 0; j < 3; j++) {
        int H = lane + 32 * j;
        ehp[H] = vh[j] * inv;
        ewp[H] = vw[j] * inv;
    }
}

// ---------------- out_h ----------------
__global__ __launch_bounds__(256)
void outh_kernel(const float* __restrict__ vh, const float* __restrict__ ah,
                 float* __restrict__ oh)
{
    extern __shared__ float sm[];
    float* As = sm;
    float* Vs = sm + 96 * 96;
    const int w = blockIdx.x;
    const int c0 = blockIdx.y * 32;
    const int b = blockIdx.z;
    const int tid = threadIdx.x;

    const float* ab = ah + ((size_t)b * WW + w) * 9216;
    for (int l = tid; l < 9216; l += 256) As[l] = ab[l];
    for (int l = tid; l < 96 * 32; l += 256) {
        int Hc = l / 32, c = l % 32;
        Vs[Hc * 32 + c] = vh[((size_t)b * CC + c0 + c) * HW + Hc * WW + w];
    }
    __syncthreads();

    const int c = tid % 32;
    const int hg = tid / 32;
    float acc[12];
#pragma unroll
    for (int k = 0; k < 12; k++) acc[k] = 0.f;
    for (int Hc = 0; Hc < 96; ++Hc) {
        float v = Vs[Hc * 32 + c];
#pragma unroll
        for (int k = 0; k < 12; k++)
            acc[k] += v * As[(hg * 12 + k) * 96 + Hc];
    }
#pragma unroll
    for (int k = 0; k < 12; k++) {
        int h = hg * 12 + k;
        oh[((size_t)b * CC + c0 + c) * HW + h * WW + w] = acc[k];
    }
}

// ---------------- out_w ----------------
__global__ __launch_bounds__(256)
void outw_kernel(const float* __restrict__ vw, const float* __restrict__ aw,
                 float* __restrict__ ow)
{
    extern __shared__ float sm[];
    float* As = sm;
    float* Vs = sm + 96 * 96;
    const int h = blockIdx.x;
    const int c0 = blockIdx.y * 32;
    const int b = blockIdx.z;
    const int tid = threadIdx.x;

    const float* ab = aw + ((size_t)b * HH + h) * 9216;
    for (int l = tid; l < 9216; l += 256) As[l] = ab[l];
    for (int l = tid; l < 96 * 32; l += 256) {
        int c = l / 96, Wc = l % 96;
        Vs[Wc * 33 + c] = vw[((size_t)b * CC + c0 + c) * HW + (size_t)h * WW + Wc];
    }
    __syncthreads();

    const int c = tid % 32;
    const int wg = tid / 32;
    float acc[12];
#pragma unroll
    for (int k = 0; k < 12; k++) acc[k] = 0.f;
    for (int Wc = 0; Wc < 96; ++Wc) {
        float v = Vs[Wc * 33 + c];
#pragma unroll
        for (int k = 0; k < 12; k++)
            acc[k] += v * As[(wg * 12 + k) * 96 + Wc];
    }
#pragma unroll
    for (int k = 0; k < 12; k++) {
        int w = wg * 12 + k;
        ow[((size_t)b * CC + c0 + c) * HW + (size_t)h * WW + w] = acc[k];
    }
}

// ---------------- final combine ----------------
__global__ __launch_bounds__(256)
void combine_kernel(const float* __restrict__ x, const float* __restrict__ oh,
                    const float* __restrict__ ow, const float* __restrict__ gamma,
                    float* __restrict__ out)
{
    size_t i = (size_t)blockIdx.x * 256 + threadIdx.x;
    const float4* x4 = (const float4*)x;
    const float4* a4 = (const float4*)oh;
    const float4* b4 = (const float4*)ow;
    float4* o4 = (float4*)out;
    float g = gamma[0];
    float4 xa = x4[i], aa = a4[i], bb = b4[i];
    float4 r;
    r.x = g * (aa.x + bb.x) + xa.x;
    r.y = g * (aa.y + bb.y) + xa.y;
    r.z = g * (aa.z + bb.z) + xa.z;
    r.w = g * (aa.w + bb.w) + xa.w;
    o4[i] = r;
}

// ---------------- launch ----------------
extern "C" void kernel_launch(void* const* d_in, const int* in_sizes, int n_in,
                              void* d_out, int out_size)
{
    const float* x    = (const float*)d_in[0];
    const float* wq_h = (const float*)d_in[1];
    const float* bq_h = (const float*)d_in[2];
    const float* wq_w = (const float*)d_in[3];
    const float* bq_w = (const float*)d_in[4];
    const float* wk_h = (const float*)d_in[5];
    const float* bk_h = (const float*)d_in[6];
    const float* wk_w = (const float*)d_in[7];
    const float* bk_w = (const float*)d_in[8];
    const float* wv_h = (const float*)d_in[9];
    const float* bv_h = (const float*)d_in[10];
    const float* wv_w = (const float*)d_in[11];
    const float* bv_w = (const float*)d_in[12];
    const float* gamma= (const float*)d_in[13];
    float* out = (float*)d_out;

    __half *Awhv, *Awlv, *Awhh, *Awlh, *xth, *xtl;
    float *qh, *qw, *kh, *kw, *vh, *vw, *eh, *ew, *oh, *ow;
    cudaGetSymbolAddress((void**)&Awhv, g_Awh_v);
    cudaGetSymbolAddress((void**)&Awlv, g_Awl_v);
    cudaGetSymbolAddress((void**)&Awhh, g_Awh_h);
    cudaGetSymbolAddress((void**)&Awlh, g_Awl_h);
    cudaGetSymbolAddress((void**)&xth, g_xth);
    cudaGetSymbolAddress((void**)&xtl, g_xtl);
    cudaGetSymbolAddress((void**)&qh, g_qh);
    cudaGetSymbolAddress((void**)&qw, g_qw);
    cudaGetSymbolAddress((void**)&kh, g_kh);
    cudaGetSymbolAddress((void**)&kw, g_kw);
    cudaGetSymbolAddress((void**)&vh, g_vh);
    cudaGetSymbolAddress((void**)&vw, g_vw);
    cudaGetSymbolAddress((void**)&eh, g_eh);
    cudaGetSymbolAddress((void**)&ew, g_ew);
    cudaGetSymbolAddress((void**)&oh, g_oh);
    cudaGetSymbolAddress((void**)&ow, g_ow);

    // 1) prep
    packW_kernel<<<(384 * KDIM + 255) / 256, 256>>>(wv_h, wq_h, wk_h, Awhv, Awlv);
    packW_kernel<<<(384 * KDIM + 255) / 256, 256>>>(wv_w, wq_w, wk_w, Awhh, Awlh);
    dim3 gx(HW / 32, CC / 32, BB);
    xsplit_kernel<<<gx, 256>>>(x, xth, xtl);

    // 2) conv GEMMs: V (1-MMA fast path) + QK (3-MMA precision path)
    cudaFuncSetAttribute(conv_v_kernel, cudaFuncAttributeMaxDynamicSharedMemorySize, 2 * STG_V);
    cudaFuncSetAttribute(conv_qk_kernel, cudaFuncAttributeMaxDynamicSharedMemorySize, 2 * STG_QK);
    dim3 gv(HW / 128, 2, BB);
    dim3 gq(HW / 128, 1, BB);
    conv_v_kernel<<<gv, 256, 2 * STG_V>>>(xth, Awhv, bv_h, vh, 1);
    conv_qk_kernel<<<gq, 256, 2 * STG_QK>>>(xth, xtl, Awhv, Awlv, bq_h, bk_h, qh, kh, 1);
    conv_v_kernel<<<gv, 256, 2 * STG_V>>>(xth, Awhh, bv_w, vw, 0);
    conv_qk_kernel<<<gq, 256, 2 * STG_QK>>>(xth, xtl, Awhh, Awlh, bq_w, bk_w, qw, kw, 0);

    // 3) attention scores
    dim3 ge(96, BB);
    eh_kernel<<<ge, 256>>>(qh, kh, eh);
    ew_kernel<<<ge, 256>>>(qw, kw, ew);

    // 4) softmax
    softmax_kernel<<<(BB * HW) / 8, 256>>>(eh, ew);

    // 5) attention outputs
    size_t smemO = (9216 + 96 * 32) * sizeof(float);
    size_t smemW = (9216 + 96 * 33) * sizeof(float);
    cudaFuncSetAttribute(outh_kernel, cudaFuncAttributeMaxDynamicSharedMemorySize, 51200);
    cudaFuncSetAttribute(outw_kernel, cudaFuncAttributeMaxDynamicSharedMemorySize, 51200);
    dim3 go(96, CC / 32, BB);
    outh_kernel<<<go, 256, smemO>>>(vh, eh, oh);
    outw_kernel<<<go, 256, smemW>>>(vw, ew, ow);

    // 6) combine
    combine_kernel<<<(BB * CC * HW) / 4 / 256, 256>>>(x, oh, ow, gamma, out);
}

// round 12
// speedup vs baseline: 4.9197x; 1.1640x over previous
#include <cuda_runtime.h>
#include <cuda_fp16.h>
#include <cstdint>

// Problem constants
#define BB 16
#define CC 256
#define C8 32
#define HH 96
#define WW 96
#define HW (HH*WW)          // 9216
#define KK 11
#define KDIM (KK*CC)        // 2816
#define NCHUNK 44           // KDIM / 64

// ---------------- scratch ----------------
#define SZ_SMALL (BB*C8*HW)
#define SZ_BIG   ((size_t)BB*CC*HW)
#define SZ_E     ((size_t)BB*HH*WW*96)
#define SZ_A     (384*KDIM)
#define SZ_XT    ((size_t)BB*HW*CC)

__device__ __half g_Awh_v[SZ_A];
__device__ __half g_Awl_v[SZ_A];
__device__ __half g_Awh_h[SZ_A];
__device__ __half g_Awl_h[SZ_A];
__device__ __half g_xth[SZ_XT];
__device__ __half g_xtl[SZ_XT];
// NOTE: q/k/v/oh/ow are now stored channels-last: [b][p][c]
__device__ float g_qh[SZ_SMALL];
__device__ float g_qw[SZ_SMALL];
__device__ float g_kh[SZ_SMALL];
__device__ float g_kw[SZ_SMALL];
__device__ float g_vh[SZ_BIG];
__device__ float g_vw[SZ_BIG];
__device__ float g_eh[SZ_E];
__device__ float g_ew[SZ_E];
__device__ float g_oh[SZ_BIG];
__device__ float g_ow[SZ_BIG];

// ---------------- warp-MMA helpers (sm_80+ PTX only) ----------------
__device__ __forceinline__ uint32_t smem_u32(const void* p) {
    uint32_t a;
    asm("{ .reg .u64 t; cvta.to.shared.u64 t, %1; cvt.u32.u64 %0, t; }" : "=r"(a) : "l"(p));
    return a;
}
__device__ __forceinline__ void ldmx4(uint32_t* r, uint32_t addr) {
    asm volatile("ldmatrix.sync.aligned.m8n8.x4.shared.b16 {%0,%1,%2,%3}, [%4];"
        : "=r"(r[0]), "=r"(r[1]), "=r"(r[2]), "=r"(r[3]) : "r"(addr));
}
__device__ __forceinline__ void mma16816(float* d, const uint32_t* a, const uint32_t* b) {
    asm volatile("mma.sync.aligned.m16n8k16.row.col.f32.f16.f16.f32 "
        "{%0,%1,%2,%3}, {%4,%5,%6,%7}, {%8,%9}, {%0,%1,%2,%3};"
        : "+f"(d[0]), "+f"(d[1]), "+f"(d[2]), "+f"(d[3])
        : "r"(a[0]), "r"(a[1]), "r"(a[2]), "r"(a[3]), "r"(b[0]), "r"(b[1]));
}
#define CPA16(dst, src) asm volatile("cp.async.cg.shared.global [%0], [%1], 16;" :: "r"(dst), "l"(src))
#define CPA_COMMIT() asm volatile("cp.async.commit_group;" ::: "memory")
#define CPA_WAIT1()  asm volatile("cp.async.wait_group 1;" ::: "memory")
#define CPA_WAIT0()  asm volatile("cp.async.wait_group 0;" ::: "memory")

// ---------------- prep: pack weights [o][k=t*256+c] fp16 hi/lo (v,q,k fused, 384 rows) ----------------
__global__ __launch_bounds__(256)
void packW_kernel(const float* __restrict__ wv, const float* __restrict__ wq,
                  const float* __restrict__ wk,
                  __half* __restrict__ Awh, __half* __restrict__ Awl)
{
    int idx = blockIdx.x * 256 + threadIdx.x;
    if (idx >= 384 * KDIM) return;
    int o = idx / KDIM;
    int k = idx % KDIM;
    int t = k >> 8;
    int c = k & 255;
    float v = 0.f;
    if (o < 256)      v = wv[((size_t)o * 256 + c) * 11 + t];
    else if (o < 288) v = wq[((size_t)(o - 256) * 256 + c) * 11 + t];
    else if (o < 320) v = wk[((size_t)(o - 288) * 256 + c) * 11 + t];
    __half h = __float2half_rn(v);
    Awh[idx] = h;
    Awl[idx] = __float2half_rn(v - __half2float(h));
}

// ---------------- prep: x split + transpose to [b][p][c] fp16 hi/lo ----------------
__global__ __launch_bounds__(256)
void xsplit_kernel(const float* __restrict__ x,
                   __half* __restrict__ xh, __half* __restrict__ xl)
{
    __shared__ float tile[32][33];
    const int b = blockIdx.z;
    const int c0 = blockIdx.y * 32;
    const int p0 = blockIdx.x * 32;
    const int tx = threadIdx.x & 31;
    const int ty = threadIdx.x >> 5;   // 0..7
#pragma unroll
    for (int i = 0; i < 4; i++) {
        int ci = ty + i * 8;
        tile[ci][tx] = x[((size_t)b * CC + c0 + ci) * HW + p0 + tx];
    }
    __syncthreads();
#pragma unroll
    for (int i = 0; i < 4; i++) {
        int pi = ty + i * 8;
        float v = tile[tx][pi];
        size_t o = ((size_t)b * HW + p0 + pi) * CC + c0 + tx;
        __half h = __float2half_rn(v);
        xh[o] = h;
        xl[o] = __float2half_rn(v - __half2float(h));
    }
}

#define SROW 72
#define ARR_B128 (128*SROW*2)   // 18432
#define ARR_A64  (64*SROW*2)    // 9216

// ---------------- V conv: M=256 (2 tiles), 1 MMA, cp.async 2-stage; OUT: vt[b][p][256] ----------------
#define STG_V (2*ARR_B128)
__global__ __launch_bounds__(256, 2)
void conv_v_kernel(const __half* __restrict__ xh,
                   const __half* __restrict__ Awh,
                   const float* __restrict__ bv,
                   float* __restrict__ vOut, int isVert)
{
    extern __shared__ char smem[];
    const uint32_t sb = smem_u32(smem);
    const int tid = threadIdx.x;
    const int lane = tid & 31;
    const int wid = tid >> 5;
    const int p0 = blockIdx.x * 128;
    const int obase = blockIdx.y * 128;
    const int bz = blockIdx.z;
    const int wm = (wid & 1) * 64;
    const int wn = (wid >> 1) * 32;

    const __half* xbh = xh + (size_t)bz * HW * CC;

    const int arow = lane & 15;
    const int akoff = (lane >> 4) << 3;
    const int brow = (lane & 7) + ((lane >> 4) << 3);
    const int bkoff = ((lane >> 3) & 1) << 3;

    auto stage_chunk = [&](int ck, int s) {
        const int t = ck >> 2;
        const int c0k = (ck & 3) << 6;
        const int sh = t - 5;
        const int off = isVert ? sh * WW : sh;
        const int k0 = t * 256 + c0k;
        const uint32_t sA = sb + (uint32_t)s * STG_V;
        const uint32_t sB = sA + ARR_B128;
#pragma unroll
        for (int i = 0; i < 4; i++) {
            int idx = tid + i * 256;
            int r = idx >> 3, c16 = idx & 7;
            uint32_t so = (uint32_t)(r * (SROW * 2) + c16 * 16);
            CPA16(sA + so, Awh + (size_t)(obase + r) * KDIM + k0 + c16 * 8);
        }
#pragma unroll
        for (int i = 0; i < 4; i++) {
            int idx = tid + i * 256;
            int r = idx >> 3, c16 = idx & 7;
            int p = p0 + r;
            bool valid = isVert ? ((unsigned)(p + off) < (unsigned)HW)
                                : ((unsigned)(p % WW + sh) < (unsigned)WW);
            uint32_t so = (uint32_t)(r * (SROW * 2) + c16 * 16);
            if (valid) {
                size_t go = (size_t)(p + off) * CC + c0k + c16 * 8;
                CPA16(sB + so, xbh + go);
            } else {
                *(uint4*)(smem + (size_t)s * STG_V + ARR_B128 + so) = make_uint4(0u, 0u, 0u, 0u);
            }
        }
        CPA_COMMIT();
    };

    float acc[4][4][4];
#pragma unroll
    for (int a = 0; a < 4; a++)
#pragma unroll
        for (int b = 0; b < 4; b++)
#pragma unroll
            for (int c = 0; c < 4; c++) acc[a][b][c] = 0.f;

    stage_chunk(0, 0);
    stage_chunk(1, 1);

    for (int ck = 0; ck < NCHUNK; ck++) {
        const int s = ck & 1;
        if (ck == NCHUNK - 1) { CPA_WAIT0(); } else { CPA_WAIT1(); }
        __syncthreads();
        const uint32_t sA = sb + (uint32_t)s * STG_V;
        const uint32_t sB = sA + ARR_B128;

#pragma unroll
        for (int k16 = 0; k16 < 4; k16++) {
            const int kb = k16 * 16;
            uint32_t bh[2][4];
#pragma unroll
            for (int ng = 0; ng < 2; ng++) {
                uint32_t boff = (uint32_t)(((wn + ng * 16 + brow) * SROW + kb + bkoff) * 2);
                ldmx4(bh[ng], sB + boff);
            }
#pragma unroll
            for (int mi = 0; mi < 4; mi++) {
                uint32_t aoff = (uint32_t)(((wm + mi * 16 + arow) * SROW + kb + akoff) * 2);
                uint32_t ah[4];
                ldmx4(ah, sA + aoff);
#pragma unroll
                for (int ni = 0; ni < 4; ni++)
                    mma16816(acc[mi][ni], ah, &bh[ni >> 1][(ni & 1) * 2]);
            }
        }
        __syncthreads();
        if (ck + 2 < NCHUNK) stage_chunk(ck + 2, s);
    }

    // ---- transpose epilogue via smem: write vt[b][p][c] coalesced ----
    float* ts = (float*)smem;   // [128 p][132]
#pragma unroll
    for (int mi = 0; mi < 4; mi++) {
#pragma unroll
        for (int half_ = 0; half_ < 2; half_++) {
            int o = wm + mi * 16 + (lane >> 2) + half_ * 8;
            float b = bv[obase + o];
#pragma unroll
            for (int ni = 0; ni < 4; ni++) {
                int p = wn + ni * 8 + (lane & 3) * 2;
                ts[p * 132 + o] = acc[mi][ni][half_ * 2 + 0] + b;
                ts[(p + 1) * 132 + o] = acc[mi][ni][half_ * 2 + 1] + b;
            }
        }
    }
    __syncthreads();
    {
        int r = tid >> 1;
        int part = (tid & 1) * 64;
        float* dst = vOut + ((size_t)bz * HW + p0 + r) * CC + obase + part;
#pragma unroll
        for (int j = 0; j < 16; j++)
            *(float4*)(dst + j * 4) = *(float4*)&ts[r * 132 + part + j * 4];
    }
}

// ---------------- QK conv: M=64, 3 MMAs; OUT: qt/kt[b][p][32] ----------------
#define STG_QK (2*ARR_A64 + 2*ARR_B128)
__global__ __launch_bounds__(256, 2)
void conv_qk_kernel(const __half* __restrict__ xh, const __half* __restrict__ xl,
                    const __half* __restrict__ Awh, const __half* __restrict__ Awl,
                    const float* __restrict__ bq, const float* __restrict__ bk,
                    float* __restrict__ qOut, float* __restrict__ kOut, int isVert)
{
    extern __shared__ char smem[];
    const uint32_t sb = smem_u32(smem);
    const int tid = threadIdx.x;
    const int lane = tid & 31;
    const int wid = tid >> 5;
    const int p0 = blockIdx.x * 128;
    const int bz = blockIdx.z;
    const int wn16 = wid * 16;

    const __half* xbh = xh + (size_t)bz * HW * CC;
    const __half* xbl = xl + (size_t)bz * HW * CC;

    const int arow = lane & 15;
    const int akoff = (lane >> 4) << 3;
    const int brow = (lane & 7) + ((lane >> 4) << 3);
    const int bkoff = ((lane >> 3) & 1) << 3;

    auto stage_chunk = [&](int ck, int s) {
        const int t = ck >> 2;
        const int c0k = (ck & 3) << 6;
        const int sh = t - 5;
        const int off = isVert ? sh * WW : sh;
        const int k0 = t * 256 + c0k;
        const uint32_t sAh = sb + (uint32_t)s * STG_QK;
        const uint32_t sAl = sAh + ARR_A64;
        const uint32_t sBh = sAl + ARR_A64;
        const uint32_t sBl = sBh + ARR_B128;
#pragma unroll
        for (int i = 0; i < 2; i++) {
            int idx = tid + i * 256;
            int r = idx >> 3, c16 = idx & 7;
            uint32_t so = (uint32_t)(r * (SROW * 2) + c16 * 16);
            size_t go = (size_t)(256 + r) * KDIM + k0 + c16 * 8;
            CPA16(sAh + so, Awh + go);
            CPA16(sAl + so, Awl + go);
        }
#pragma unroll
        for (int i = 0; i < 4; i++) {
            int idx = tid + i * 256;
            int r = idx >> 3, c16 = idx & 7;
            int p = p0 + r;
            bool valid = isVert ? ((unsigned)(p + off) < (unsigned)HW)
                                : ((unsigned)(p % WW + sh) < (unsigned)WW);
            uint32_t so = (uint32_t)(r * (SROW * 2) + c16 * 16);
            if (valid) {
                size_t go = (size_t)(p + off) * CC + c0k + c16 * 8;
                CPA16(sBh + so, xbh + go);
                CPA16(sBl + so, xbl + go);
            } else {
                uint4 z = make_uint4(0u, 0u, 0u, 0u);
                *(uint4*)(smem + (size_t)s * STG_QK + 2 * ARR_A64 + so) = z;
                *(uint4*)(smem + (size_t)s * STG_QK + 2 * ARR_A64 + ARR_B128 + so) = z;
            }
        }
        CPA_COMMIT();
    };

    float acc[4][2][4];
#pragma unroll
    for (int a = 0; a < 4; a++)
#pragma unroll
        for (int b = 0; b < 2; b++)
#pragma unroll
            for (int c = 0; c < 4; c++) acc[a][b][c] = 0.f;

    stage_chunk(0, 0);
    stage_chunk(1, 1);

    for (int ck = 0; ck < NCHUNK; ck++) {
        const int s = ck & 1;
        if (ck == NCHUNK - 1) { CPA_WAIT0(); } else { CPA_WAIT1(); }
        __syncthreads();
        const uint32_t sAh = sb + (uint32_t)s * STG_QK;
        const uint32_t sAl = sAh + ARR_A64;
        const uint32_t sBh = sAl + ARR_A64;
        const uint32_t sBl = sBh + ARR_B128;

#pragma unroll
        for (int k16 = 0; k16 < 4; k16++) {
            const int kb = k16 * 16;
            uint32_t bh[4], bl[4];
            uint32_t boff = (uint32_t)(((wn16 + brow) * SROW + kb + bkoff) * 2);
            ldmx4(bh, sBh + boff);
            ldmx4(bl, sBl + boff);
#pragma unroll
            for (int mi = 0; mi < 4; mi++) {
                uint32_t aoff = (uint32_t)(((mi * 16 + arow) * SROW + kb + akoff) * 2);
                uint32_t ah[4], al[4];
                ldmx4(ah, sAh + aoff);
                ldmx4(al, sAl + aoff);
#pragma unroll
                for (int ni = 0; ni < 2; ni++) {
                    mma16816(acc[mi][ni], ah, &bh[ni * 2]);
                    mma16816(acc[mi][ni], ah, &bl[ni * 2]);
                    mma16816(acc[mi][ni], al, &bh[ni * 2]);
                }
            }
        }
        __syncthreads();
        if (ck + 2 < NCHUNK) stage_chunk(ck + 2, s);
    }

    // ---- transpose epilogue: write qt/kt[b][p][32] coalesced ----
    float* ts = (float*)smem;   // [128 p][68]
#pragma unroll
    for (int mi = 0; mi < 4; mi++) {
#pragma unroll
        for (int half_ = 0; half_ < 2; half_++) {
            int rr = mi * 16 + (lane >> 2) + half_ * 8;  // 0..63
            float b = (rr < 32) ? bq[rr] : bk[rr - 32];
#pragma unroll
            for (int ni = 0; ni < 2; ni++) {
                int p = wn16 + ni * 8 + (lane & 3) * 2;
                ts[p * 68 + rr] = acc[mi][ni][half_ * 2 + 0] + b;
                ts[(p + 1) * 68 + rr] = acc[mi][ni][half_ * 2 + 1] + b;
            }
        }
    }
    __syncthreads();
    {
        int r = tid >> 1;
        int part = (tid & 1) * 32;     // 0 -> q, 32 -> k
        float* dst = ((tid & 1) == 0 ? qOut : kOut) + ((size_t)bz * HW + p0 + r) * C8;
#pragma unroll
        for (int j = 0; j < 8; j++)
            *(float4*)(dst + j * 4) = *(float4*)&ts[r * 68 + part + j * 4];
    }
}

// ---------------- e_h: per (b,w), E[h][H] = sum_c Q[h][c] K[H][c]  (qt/kt [b][p][32]) ----------------
__global__ __launch_bounds__(256)
void eh_kernel(const float* __restrict__ qt, const float* __restrict__ kt,
               float* __restrict__ eh)
{
    const int w = blockIdx.x;
    const int b = blockIdx.y;
    __shared__ float Qs[HH][33];
    __shared__ float Ks[HH][33];
    const int tid = threadIdx.x;
    const float* qb = qt + (size_t)b * HW * C8;
    const float* kb = kt + (size_t)b * HW * C8;
    for (int l = tid; l < HH * C8; l += 256) {
        int h = l >> 5, c = l & 31;
        size_t go = ((size_t)(h * WW + w)) * C8 + c;
        Qs[h][c] = qb[go];
        Ks[h][c] = kb[go];
    }
    __syncthreads();
    const int h0 = (tid / 16) * 6;
    const int H0 = (tid % 16) * 6;
    float acc[6][6];
#pragma unroll
    for (int i = 0; i < 6; i++)
#pragma unroll
        for (int j = 0; j < 6; j++) acc[i][j] = 0.f;
    for (int c = 0; c < C8; ++c) {
        float q[6], k[6];
#pragma unroll
        for (int i = 0; i < 6; i++) q[i] = Qs[h0 + i][c];
#pragma unroll
        for (int j = 0; j < 6; j++) k[j] = Ks[H0 + j][c];
#pragma unroll
        for (int i = 0; i < 6; i++)
#pragma unroll
            for (int j = 0; j < 6; j++) acc[i][j] += q[i] * k[j];
    }
    float* ep = eh + ((size_t)b * WW + w) * HH * 96;
#pragma unroll
    for (int i = 0; i < 6; i++)
#pragma unroll
        for (int j = 0; j < 6; j++)
            ep[(h0 + i) * 96 + H0 + j] = acc[i][j];
}

// ---------------- e_w: per (b,h) ----------------
__global__ __launch_bounds__(256)
void ew_kernel(const float* __restrict__ qt, const float* __restrict__ kt,
               float* __restrict__ ew)
{
    const int h = blockIdx.x;
    const int b = blockIdx.y;
    __shared__ float Qs[WW][33];
    __shared__ float Ks[WW][33];
    const int tid = threadIdx.x;
    const float* qb = qt + (size_t)b * HW * C8;
    const float* kb = kt + (size_t)b * HW * C8;
    for (int l = tid; l < WW * C8; l += 256) {
        int wv = l >> 5, c = l & 31;
        size_t go = ((size_t)(h * WW + wv)) * C8 + c;
        Qs[wv][c] = qb[go];
        Ks[wv][c] = kb[go];
    }
    __syncthreads();
    const int w0 = (tid / 16) * 6;
    const int W0 = (tid % 16) * 6;
    float acc[6][6];
#pragma unroll
    for (int i = 0; i < 6; i++)
#pragma unroll
        for (int j = 0; j < 6; j++) acc[i][j] = 0.f;
    for (int c = 0; c < C8; ++c) {
        float q[6], k[6];
#pragma unroll
        for (int i = 0; i < 6; i++) q[i] = Qs[w0 + i][c];
#pragma unroll
        for (int j = 0; j < 6; j++) k[j] = Ks[W0 + j][c];
#pragma unroll
        for (int i = 0; i < 6; i++)
#pragma unroll
            for (int j = 0; j < 6; j++) acc[i][j] += q[i] * k[j];
    }
    float* ep = ew + ((size_t)b * HH + h) * WW * 96;
#pragma unroll
    for (int i = 0; i < 6; i++)
#pragma unroll
        for (int j = 0; j < 6; j++)
            ep[(w0 + i) * 96 + W0 + j] = acc[i][j];
}

// ---------------- softmax over concat(e_h row, e_w row), in-place ----------------
__global__ __launch_bounds__(256)
void softmax_kernel(float* __restrict__ eh, float* __restrict__ ew)
{
    const int warp = threadIdx.x / 32;
    const int lane = threadIdx.x % 32;
    const int r = blockIdx.x * 8 + warp;
    const int b = r / HW;
    const int rem = r % HW;
    const int h = rem / WW;
    const int w = rem % WW;
    float* ehp = eh + (((size_t)b * WW + w) * HH + h) * 96;
    float* ewp = ew + (((size_t)b * HH + h) * WW + w) * 96;

    float vh[3], vw[3];
    float m = -3.0e38f;
#pragma unroll
    for (int j = 0; j < 3; j++) {
        int H = lane + 32 * j;
        float a = (H == h) ? -3.0e38f : ehp[H];
        float c = ewp[H];
        vh[j] = a; vw[j] = c;
        m = fmaxf(m, fmaxf(a, c));
    }
#pragma unroll
    for (int s = 16; s > 0; s >>= 1)
        m = fmaxf(m, __shfl_xor_sync(0xffffffffu, m, s));
    float sum = 0.f;
#pragma unroll
    for (int j = 0; j < 3; j++) {
        vh[j] = __expf(vh[j] - m);
        vw[j] = __expf(vw[j] - m);
        sum += vh[j] + vw[j];
    }
#pragma unroll
    for (int s = 16; s > 0; s >>= 1)
        sum += __shfl_xor_sync(0xffffffffu, sum, s);
    float inv = 1.0f / sum;
#pragma unroll
    for (int j = 0; j < 3; j++) {
        int H = lane + 32 * j;
        ehp[H] = vh[j] * inv;
        ewp[H] = vw[j] * inv;
    }
}

// ---------------- out_h: per (b,w): ot[h][c] = sum_H A[h][H] * Vt[H][c]; all layouts [p][c] ----------------
__global__ __launch_bounds__(256)
void outh_kernel(const float* __restrict__ vt, const float* __restrict__ ah,
                 float* __restrict__ oh)
{
    extern __shared__ float sm[];
    float* As = sm;            // [96][96]
    float* Vs = sm + 9216;     // [96][32]
    const int w = blockIdx.x;
    const int b = blockIdx.y;
    const int tid = threadIdx.x;

    const float* ab = ah + ((size_t)b * WW + w) * 9216;
    for (int l = tid; l < 9216; l += 256) As[l] = ab[l];

    const float* vb = vt + (size_t)b * HW * CC;
    const int c = tid & 31;
    const int hg = tid >> 5;

    for (int c0 = 0; c0 < CC; c0 += 32) {
        __syncthreads();
        for (int l = tid; l < 96 * 32; l += 256) {
            int H = l >> 5, cc = l & 31;
            Vs[l] = vb[((size_t)(H * WW + w)) * CC + c0 + cc];
        }
        __syncthreads();
        float acc[12];
#pragma unroll
        for (int k = 0; k < 12; k++) acc[k] = 0.f;
        for (int H4 = 0; H4 < 96; H4 += 4) {
            float v0 = Vs[(H4 + 0) * 32 + c];
            float v1 = Vs[(H4 + 1) * 32 + c];
            float v2 = Vs[(H4 + 2) * 32 + c];
            float v3 = Vs[(H4 + 3) * 32 + c];
#pragma unroll
            for (int k = 0; k < 12; k++) {
                float4 a4 = *(const float4*)&As[(hg * 12 + k) * 96 + H4];
                acc[k] += a4.x * v0 + a4.y * v1 + a4.z * v2 + a4.w * v3;
            }
        }
#pragma unroll
        for (int k = 0; k < 12; k++) {
            int h = hg * 12 + k;
            oh[((size_t)b * HW + h * WW + w) * CC + c0 + c] = acc[k];
        }
    }
}

// ---------------- out_w: per (b,h) ----------------
__global__ __launch_bounds__(256)
void outw_kernel(const float* __restrict__ vt, const float* __restrict__ aw,
                 float* __restrict__ ow)
{
    extern __shared__ float sm[];
    float* As = sm;            // [96][96]
    float* Vs = sm + 9216;     // [96][32]
    const int h = blockIdx.x;
    const int b = blockIdx.y;
    const int tid = threadIdx.x;

    const float* ab = aw + ((size_t)b * HH + h) * 9216;
    for (int l = tid; l < 9216; l += 256) As[l] = ab[l];

    const float* vb = vt + (size_t)b * HW * CC;
    const int c = tid & 31;
    const int wg = tid >> 5;

    for (int c0 = 0; c0 < CC; c0 += 32) {
        __syncthreads();
        for (int l = tid; l < 96 * 32; l += 256) {
            int W = l >> 5, cc = l & 31;
            Vs[l] = vb[((size_t)(h * WW + W)) * CC + c0 + cc];
        }
        __syncthreads();
        float acc[12];
#pragma unroll
        for (int k = 0; k < 12; k++) acc[k] = 0.f;
        for (int W4 = 0; W4 < 96; W4 += 4) {
            float v0 = Vs[(W4 + 0) * 32 + c];
            float v1 = Vs[(W4 + 1) * 32 + c];
            float v2 = Vs[(W4 + 2) * 32 + c];
            float v3 = Vs[(W4 + 3) * 32 + c];
#pragma unroll
            for (int k = 0; k < 12; k++) {
                float4 a4 = *(const float4*)&As[(wg * 12 + k) * 96 + W4];
                acc[k] += a4.x * v0 + a4.y * v1 + a4.z * v2 + a4.w * v3;
            }
        }
#pragma unroll
        for (int k = 0; k < 12; k++) {
            int w = wg * 12 + k;
            ow[((size_t)b * HW + h * WW + w) * CC + c0 + c] = acc[k];
        }
    }
}

// ---------------- combine: out[b][c][p] = gamma*(oh+ow)[b][p][c] + x[b][c][p] (smem transpose) ----------------
__global__ __launch_bounds__(256)
void combine_kernel(const float* __restrict__ x, const float* __restrict__ oh,
                    const float* __restrict__ ow, const float* __restrict__ gamma,
                    float* __restrict__ out)
{
    __shared__ float tile[32][33];
    const int b = blockIdx.z;
    const int c0 = blockIdx.y * 32;
    const int p0 = blockIdx.x * 32;
    const int tx = threadIdx.x & 31;
    const int ty = threadIdx.x >> 5;
    float g = gamma[0];
#pragma unroll
    for (int i = 0; i < 4; i++) {
        int pi = ty + i * 8;
        size_t po = ((size_t)b * HW + p0 + pi) * CC + c0 + tx;
        tile[pi][tx] = g * (oh[po] + ow[po]);
    }
    __syncthreads();
#pragma unroll
    for (int i = 0; i < 4; i++) {
        int ci = ty + i * 8;
        size_t xo = ((size_t)b * CC + c0 + ci) * HW + p0 + tx;
        out[xo] = tile[tx][ci] + x[xo];
    }
}

// ---------------- launch ----------------
extern "C" void kernel_launch(void* const* d_in, const int* in_sizes, int n_in,
                              void* d_out, int out_size)
{
    const float* x    = (const float*)d_in[0];
    const float* wq_h = (const float*)d_in[1];
    const float* bq_h = (const float*)d_in[2];
    const float* wq_w = (const float*)d_in[3];
    const float* bq_w = (const float*)d_in[4];
    const float* wk_h = (const float*)d_in[5];
    const float* bk_h = (const float*)d_in[6];
    const float* wk_w = (const float*)d_in[7];
    const float* bk_w = (const float*)d_in[8];
    const float* wv_h = (const float*)d_in[9];
    const float* bv_h = (const float*)d_in[10];
    const float* wv_w = (const float*)d_in[11];
    const float* bv_w = (const float*)d_in[12];
    const float* gamma= (const float*)d_in[13];
    float* out = (float*)d_out;

    __half *Awhv, *Awlv, *Awhh, *Awlh, *xth, *xtl;
    float *qh, *qw, *kh, *kw, *vh, *vw, *eh, *ew, *oh, *ow;
    cudaGetSymbolAddress((void**)&Awhv, g_Awh_v);
    cudaGetSymbolAddress((void**)&Awlv, g_Awl_v);
    cudaGetSymbolAddress((void**)&Awhh, g_Awh_h);
    cudaGetSymbolAddress((void**)&Awlh, g_Awl_h);
    cudaGetSymbolAddress((void**)&xth, g_xth);
    cudaGetSymbolAddress((void**)&xtl, g_xtl);
    cudaGetSymbolAddress((void**)&qh, g_qh);
    cudaGetSymbolAddress((void**)&qw, g_qw);
    cudaGetSymbolAddress((void**)&kh, g_kh);
    cudaGetSymbolAddress((void**)&kw, g_kw);
    cudaGetSymbolAddress((void**)&vh, g_vh);
    cudaGetSymbolAddress((void**)&vw, g_vw);
    cudaGetSymbolAddress((void**)&eh, g_eh);
    cudaGetSymbolAddress((void**)&ew, g_ew);
    cudaGetSymbolAddress((void**)&oh, g_oh);
    cudaGetSymbolAddress((void**)&ow, g_ow);

    // 1) prep
    packW_kernel<<<(384 * KDIM + 255) / 256, 256>>>(wv_h, wq_h, wk_h, Awhv, Awlv);
    packW_kernel<<<(384 * KDIM + 255) / 256, 256>>>(wv_w, wq_w, wk_w, Awhh, Awlh);
    dim3 gx(HW / 32, CC / 32, BB);
    xsplit_kernel<<<gx, 256>>>(x, xth, xtl);

    // 2) conv GEMMs (channels-last outputs)
    cudaFuncSetAttribute(conv_v_kernel, cudaFuncAttributeMaxDynamicSharedMemorySize, 2 * STG_V);
    cudaFuncSetAttribute(conv_qk_kernel, cudaFuncAttributeMaxDynamicSharedMemorySize, 2 * STG_QK);
    dim3 gv(HW / 128, 2, BB);
    dim3 gq(HW / 128, 1, BB);
    conv_v_kernel<<<gv, 256, 2 * STG_V>>>(xth, Awhv, bv_h, vh, 1);
    conv_qk_kernel<<<gq, 256, 2 * STG_QK>>>(xth, xtl, Awhv, Awlv, bq_h, bk_h, qh, kh, 1);
    conv_v_kernel<<<gv, 256, 2 * STG_V>>>(xth, Awhh, bv_w, vw, 0);
    conv_qk_kernel<<<gq, 256, 2 * STG_QK>>>(xth, xtl, Awhh, Awlh, bq_w, bk_w, qw, kw, 0);

    // 3) attention scores
    dim3 ge(96, BB);
    eh_kernel<<<ge, 256>>>(qh, kh, eh);
    ew_kernel<<<ge, 256>>>(qw, kw, ew);

    // 4) softmax
    softmax_kernel<<<(BB * HW) / 8, 256>>>(eh, ew);

    // 5) attention outputs (channels-last)
    size_t smemA = (9216 + 96 * 32) * sizeof(float);   // 49152
    cudaFuncSetAttribute(outh_kernel, cudaFuncAttributeMaxDynamicSharedMemorySize, 51200);
    cudaFuncSetAttribute(outw_kernel, cudaFuncAttributeMaxDynamicSharedMemorySize, 51200);
    outh_kernel<<<ge, 256, smemA>>>(vh, eh, oh);
    outw_kernel<<<ge, 256, smemA>>>(vw, ew, ow);

    // 6) combine + transpose back to [b][c][p]
    combine_kernel<<<gx, 256>>>(x, oh, ow, gamma, out);
}